// round 5
// baseline (speedup 1.0000x reference)
#include <cuda_runtime.h>
#include <math.h>

// ---------------- problem constants ----------------
#define BB   32
#define TT   512
#define DENC 512
#define HH   640
#define VV   4096
#define MM   (BB*TT)        // 16384
#define H4   (4*HH)         // 2560
#define OUT0 ((size_t)MM*VV) // 67108864

// ---------------- scratch (device globals; no allocation) ----------------
__device__ __align__(16) float g_x[BB*HH];
__device__ __align__(16) float g_gates[BB*H4];
__device__ __align__(16) float g_h0[BB*HH];
__device__ __align__(16) float g_c0[BB*HH];
__device__ __align__(16) float g_h1[BB*HH];
__device__ __align__(16) float g_c1[BB*HH];
__device__ __align__(16) float g_g[BB*HH];
__device__ __align__(16) float g_f[(size_t)MM*HH];   // 42 MB
__device__ int g_tok[BB];

// ---------------- token sniff + decode ----------------
// targets is declared int64 in the reference but JAX (x64 off) materializes
// int32. Detect which layout is actually in memory by inspecting the first
// 128 bytes (safe for either dtype): little-endian int64 tokens < 2^31 have
// all odd 32-bit words == 0; random int32 tokens in [0,4096) do not.
__global__ void k_tok(const int* __restrict__ t)
{
    if (threadIdx.x == 0) {
        bool is64 = true;
        #pragma unroll
        for (int i = 1; i < 32; i += 2)
            if (t[i] != 0) { is64 = false; break; }
        for (int b = 0; b < BB; b++) {
            int tok = is64 ? t[2*b] : t[b];
            if (tok < 0) tok = 0;
            if (tok >= VV) tok = VV - 1;
            g_tok[b] = tok;
        }
    }
}

// ---------------- embedding gather ----------------
__global__ void k_embed(const float* __restrict__ embed)
{
    int i = blockIdx.x*blockDim.x + threadIdx.x;
    if (i >= BB*HH) return;
    int b = i / HH, k = i % HH;
    g_x[i] = embed[(size_t)g_tok[b]*HH + k];
}

// ---------------- small GEMM: C[32][N] = A@W^T (+A2@W2^T) + b1 (+b2) ----------------
__global__ __launch_bounds__(256) void k_small(
    const float* __restrict__ A,  const float* __restrict__ A2,
    const float* __restrict__ W,  const float* __restrict__ W2,
    const float* __restrict__ b1, const float* __restrict__ b2,
    float* __restrict__ C, int N, int K)
{
    __shared__ float As [32][33];
    __shared__ float A2s[32][33];
    __shared__ float Ws [32][33];
    __shared__ float W2s[32][33];

    int tid = threadIdx.x;
    int n0  = blockIdx.x * 32;
    int m   = tid & 31;
    int nid = tid >> 5;              // 0..7
    int lrow = tid >> 3;             // 0..31
    int lcol = (tid & 7) * 4;        // 0..28 step 4
    bool dual = (A2 != nullptr);

    float acc[4] = {0.f, 0.f, 0.f, 0.f};

    for (int k0 = 0; k0 < K; k0 += 32) {
        float4 v = *(const float4*)(A + (size_t)lrow*K + k0 + lcol);
        As[lrow][lcol+0]=v.x; As[lrow][lcol+1]=v.y; As[lrow][lcol+2]=v.z; As[lrow][lcol+3]=v.w;
        float4 w = *(const float4*)(W + (size_t)(n0+lrow)*K + k0 + lcol);
        Ws[lrow][lcol+0]=w.x; Ws[lrow][lcol+1]=w.y; Ws[lrow][lcol+2]=w.z; Ws[lrow][lcol+3]=w.w;
        if (dual) {
            float4 v2 = *(const float4*)(A2 + (size_t)lrow*K + k0 + lcol);
            A2s[lrow][lcol+0]=v2.x; A2s[lrow][lcol+1]=v2.y; A2s[lrow][lcol+2]=v2.z; A2s[lrow][lcol+3]=v2.w;
            float4 w2 = *(const float4*)(W2 + (size_t)(n0+lrow)*K + k0 + lcol);
            W2s[lrow][lcol+0]=w2.x; W2s[lrow][lcol+1]=w2.y; W2s[lrow][lcol+2]=w2.z; W2s[lrow][lcol+3]=w2.w;
        }
        __syncthreads();
        if (dual) {
            #pragma unroll 8
            for (int kk = 0; kk < 32; kk++) {
                float av = As[m][kk], a2v = A2s[m][kk];
                #pragma unroll
                for (int j = 0; j < 4; j++) {
                    int nl = nid + 8*j;
                    acc[j] += av * Ws[nl][kk] + a2v * W2s[nl][kk];
                }
            }
        } else {
            #pragma unroll 8
            for (int kk = 0; kk < 32; kk++) {
                float av = As[m][kk];
                #pragma unroll
                for (int j = 0; j < 4; j++)
                    acc[j] += av * Ws[nid + 8*j][kk];
            }
        }
        __syncthreads();
    }
    #pragma unroll
    for (int j = 0; j < 4; j++) {
        int n = n0 + nid + 8*j;
        float bias = b1[n] + (b2 ? b2[n] : 0.f);
        C[(size_t)m*N + n] = acc[j] + bias;
    }
}

// ---------------- LSTM pointwise ----------------
__device__ __forceinline__ float sigmf(float x) { return 1.f / (1.f + expf(-x)); }

__global__ void k_lstm_act(const float* __restrict__ gates,
                           const float* __restrict__ cin,
                           float* __restrict__ h, float* __restrict__ c)
{
    int i = blockIdx.x*blockDim.x + threadIdx.x;
    if (i >= BB*HH) return;
    int m = i / HH, j = i % HH;
    const float* gr = gates + (size_t)m*H4;
    float ig = sigmf(gr[j]);
    float fg = sigmf(gr[HH + j]);
    float gg = tanhf(gr[2*HH + j]);
    float og = sigmf(gr[3*HH + j]);
    float cn = fg * cin[i] + ig * gg;
    c[i] = cn;
    h[i] = og * tanhf(cn);
}

// ---------------- GEMM1: f[m][n] = sum_d enc[b][d][t]*Wenc[n][d] + benc[n] ----------------
__global__ __launch_bounds__(256) void k_gemm_f(
    const float* __restrict__ enc, const float* __restrict__ wenc,
    const float* __restrict__ benc)
{
    __shared__ __align__(16) float As[8][132];
    __shared__ __align__(16) float Bs[8][132];

    int tid = threadIdx.x;
    int n0 = blockIdx.x * 128;
    int m0 = blockIdx.y * 128;
    int b  = m0 >> 9;            // /512 (tile never crosses batch)
    int t0 = m0 & 511;
    const float* encb = enc + (size_t)b*DENC*TT;

    int ak  = tid >> 5;          // 0..7 (k row)
    int atq = (tid & 31) * 4;    // t offset
    int brow = tid >> 1;         // 0..127
    int bkq  = (tid & 1) * 4;    // 0 or 4
    int tx = tid & 15, ty = tid >> 4;

    float acc[8][8];
    #pragma unroll
    for (int i = 0; i < 8; i++)
        #pragma unroll
        for (int j = 0; j < 8; j++) acc[i][j] = 0.f;

    for (int k0 = 0; k0 < DENC; k0 += 8) {
        float4 av = *(const float4*)(encb + (size_t)(k0+ak)*TT + t0 + atq);
        *(float4*)(&As[ak][atq]) = av;
        float4 bv = *(const float4*)(wenc + (size_t)(n0+brow)*DENC + k0 + bkq);
        Bs[bkq+0][brow]=bv.x; Bs[bkq+1][brow]=bv.y; Bs[bkq+2][brow]=bv.z; Bs[bkq+3][brow]=bv.w;
        __syncthreads();
        #pragma unroll
        for (int k = 0; k < 8; k++) {
            float4 a0 = ((const float4*)As[k])[ty];
            float4 a1 = ((const float4*)As[k])[16+ty];
            float4 b0 = ((const float4*)Bs[k])[tx];
            float4 b1 = ((const float4*)Bs[k])[16+tx];
            float a[8]  = {a0.x,a0.y,a0.z,a0.w,a1.x,a1.y,a1.z,a1.w};
            float bb[8] = {b0.x,b0.y,b0.z,b0.w,b1.x,b1.y,b1.z,b1.w};
            #pragma unroll
            for (int i = 0; i < 8; i++)
                #pragma unroll
                for (int j = 0; j < 8; j++)
                    acc[i][j] += a[i]*bb[j];
        }
        __syncthreads();
    }
    float bn[8];
    #pragma unroll
    for (int j = 0; j < 8; j++) {
        int nj = (j < 4) ? tx*4 + j : 64 + tx*4 + (j-4);
        bn[j] = benc[n0 + nj];
    }
    #pragma unroll
    for (int i = 0; i < 8; i++) {
        int m = m0 + ((i < 4) ? ty*4 + i : 64 + ty*4 + (i-4));
        float* fr = g_f + (size_t)m*HH + n0;
        float4 o0 = {acc[i][0]+bn[0], acc[i][1]+bn[1], acc[i][2]+bn[2], acc[i][3]+bn[3]};
        float4 o1 = {acc[i][4]+bn[4], acc[i][5]+bn[5], acc[i][6]+bn[6], acc[i][7]+bn[7]};
        *(float4*)(fr + tx*4)      = o0;
        *(float4*)(fr + 64 + tx*4) = o1;
    }
}

// ---------------- GEMM2: out[m][n] = sum_k relu(f[m][k]+g[b][k]) * Wout[n][k] + bout[n] ----------------
__global__ __launch_bounds__(256) void k_gemm_out(
    const float* __restrict__ wout, const float* __restrict__ bout,
    float* __restrict__ out)
{
    __shared__ __align__(16) float As[8][132];
    __shared__ __align__(16) float Bs[8][132];

    int tid = threadIdx.x;
    int n0 = blockIdx.x * 128;
    int m0 = blockIdx.y * 128;
    int b  = m0 >> 9;
    const float* gb = g_g + (size_t)b*HH;

    int arow = tid >> 1;
    int akq  = (tid & 1) * 4;
    int tx = tid & 15, ty = tid >> 4;

    float acc[8][8];
    #pragma unroll
    for (int i = 0; i < 8; i++)
        #pragma unroll
        for (int j = 0; j < 8; j++) acc[i][j] = 0.f;

    for (int k0 = 0; k0 < HH; k0 += 8) {
        float4 fv = *(const float4*)(g_f + (size_t)(m0+arow)*HH + k0 + akq);
        float4 gv = *(const float4*)(gb + k0 + akq);
        As[akq+0][arow] = fmaxf(fv.x + gv.x, 0.f);
        As[akq+1][arow] = fmaxf(fv.y + gv.y, 0.f);
        As[akq+2][arow] = fmaxf(fv.z + gv.z, 0.f);
        As[akq+3][arow] = fmaxf(fv.w + gv.w, 0.f);
        float4 bv = *(const float4*)(wout + (size_t)(n0+arow)*HH + k0 + akq);
        Bs[akq+0][arow]=bv.x; Bs[akq+1][arow]=bv.y; Bs[akq+2][arow]=bv.z; Bs[akq+3][arow]=bv.w;
        __syncthreads();
        #pragma unroll
        for (int k = 0; k < 8; k++) {
            float4 a0 = ((const float4*)As[k])[ty];
            float4 a1 = ((const float4*)As[k])[16+ty];
            float4 b0 = ((const float4*)Bs[k])[tx];
            float4 b1 = ((const float4*)Bs[k])[16+tx];
            float a[8]  = {a0.x,a0.y,a0.z,a0.w,a1.x,a1.y,a1.z,a1.w};
            float bb[8] = {b0.x,b0.y,b0.z,b0.w,b1.x,b1.y,b1.z,b1.w};
            #pragma unroll
            for (int i = 0; i < 8; i++)
                #pragma unroll
                for (int j = 0; j < 8; j++)
                    acc[i][j] += a[i]*bb[j];
        }
        __syncthreads();
    }
    float bn[8];
    #pragma unroll
    for (int j = 0; j < 8; j++) {
        int nj = (j < 4) ? tx*4 + j : 64 + tx*4 + (j-4);
        bn[j] = bout[n0 + nj];
    }
    #pragma unroll
    for (int i = 0; i < 8; i++) {
        int m = m0 + ((i < 4) ? ty*4 + i : 64 + ty*4 + (i-4));
        float* orow = out + (size_t)m*VV + n0;
        float4 o0 = {acc[i][0]+bn[0], acc[i][1]+bn[1], acc[i][2]+bn[2], acc[i][3]+bn[3]};
        float4 o1 = {acc[i][4]+bn[4], acc[i][5]+bn[5], acc[i][6]+bn[6], acc[i][7]+bn[7]};
        *(float4*)(orow + tx*4)      = o0;
        *(float4*)(orow + 64 + tx*4) = o1;
    }
}

// ---------------- tail: target_length + states (bounded) ----------------
__global__ void k_tail(const int* __restrict__ tlen, float* __restrict__ out,
                       size_t out_cap)
{
    size_t i = blockIdx.x*blockDim.x + threadIdx.x;
    size_t idx = OUT0 + i;
    if (idx >= out_cap) return;
    if (i < 32) { out[idx] = (float)tlen[i]; return; }
    size_t j = i - 32;
    const size_t S = BB*HH; // 20480
    if (j < S)            out[idx] = g_h0[j];
    else if (j < 2*S)     out[idx] = g_h1[j - S];
    else if (j < 3*S)     out[idx] = g_c0[j - 2*S];
    else if (j < 4*S)     out[idx] = g_c1[j - 3*S];
}

// ---------------- launch ----------------
extern "C" void kernel_launch(void* const* d_in, const int* in_sizes, int n_in,
                              void* d_out, int out_size)
{
    const float*      enc    = (const float*)d_in[0];
    const int*        tgt32  = (const int*)d_in[1];
    const int*        tlen   = (const int*)d_in[2];
    const float*      is1    = (const float*)d_in[3];
    const float*      is2    = (const float*)d_in[4];
    const float*      wih0   = (const float*)d_in[5];
    const float*      whh0   = (const float*)d_in[6];
    const float*      bih0   = (const float*)d_in[7];
    const float*      bhh0   = (const float*)d_in[8];
    const float*      wih1   = (const float*)d_in[9];
    const float*      whh1   = (const float*)d_in[10];
    const float*      bih1   = (const float*)d_in[11];
    const float*      bhh1   = (const float*)d_in[12];
    const float*      embed  = (const float*)d_in[13];
    const float*      wenc   = (const float*)d_in[14];
    const float*      benc   = (const float*)d_in[15];
    const float*      wpred  = (const float*)d_in[16];
    const float*      bpred  = (const float*)d_in[17];
    const float*      wout   = (const float*)d_in[18];
    const float*      bout   = (const float*)d_in[19];
    float*            out    = (float*)d_out;

    float *x, *gates, *h0, *c0, *h1, *c1, *gj;
    cudaGetSymbolAddress((void**)&x,     g_x);
    cudaGetSymbolAddress((void**)&gates, g_gates);
    cudaGetSymbolAddress((void**)&h0,    g_h0);
    cudaGetSymbolAddress((void**)&c0,    g_c0);
    cudaGetSymbolAddress((void**)&h1,    g_h1);
    cudaGetSymbolAddress((void**)&c1,    g_c1);
    cudaGetSymbolAddress((void**)&gj,    g_g);

    // decoder path
    k_tok<<<1, 32>>>(tgt32);
    k_embed<<<(BB*HH + 255)/256, 256>>>(embed);
    k_small<<<H4/32, 256>>>(x,  is1,           wih0, whh0, bih0, bhh0, gates, H4, HH);
    k_lstm_act<<<(BB*HH + 255)/256, 256>>>(gates, is2,           h0, c0);
    k_small<<<H4/32, 256>>>(h0, is1 + BB*HH,   wih1, whh1, bih1, bhh1, gates, H4, HH);
    k_lstm_act<<<(BB*HH + 255)/256, 256>>>(gates, is2 + BB*HH,   h1, c1);
    k_small<<<HH/32, 256>>>(h1, nullptr, wpred, nullptr, bpred, nullptr, gj, HH, HH);

    // joint network
    k_gemm_f  <<<dim3(HH/128, MM/128), 256>>>(enc, wenc, benc);
    k_gemm_out<<<dim3(VV/128, MM/128), 256>>>(wout, bout, out);

    // extra tuple outputs, if the harness expects them
    size_t cap = (size_t)out_size;
    if (cap > OUT0) {
        size_t tail_n = cap - OUT0;
        k_tail<<<(int)((tail_n + 255)/256), 256>>>(tlen, out, cap);
    }
}

// round 7
// speedup vs baseline: 1.9899x; 1.9899x over previous
#include <cuda_runtime.h>
#include <cuda_bf16.h>
#include <math.h>
#include <stdint.h>

// ---------------- problem constants ----------------
#define BB   32
#define TT   512
#define DENC 512
#define HH   640
#define VV   4096
#define MM   (BB*TT)        // 16384
#define H4   (4*HH)         // 2560
#define OUT0 ((size_t)MM*VV) // 67108864
#define KP1  (3*DENC)       // 1536
#define KP2  (3*HH)         // 1920

// ---------------- PTX helpers ----------------
__device__ __forceinline__ uint32_t smem_u32(const void* p) {
    uint32_t a;
    asm("{ .reg .u64 t; cvta.to.shared.u64 t, %1; cvt.u32.u64 %0, t; }" : "=r"(a) : "l"(p));
    return a;
}
#define CP_ASYNC16(sa, ga) \
    asm volatile("cp.async.cg.shared.global [%0], [%1], 16;" :: "r"(sa), "l"(ga))
#define CP_COMMIT() asm volatile("cp.async.commit_group;")
#define CP_WAIT1()  asm volatile("cp.async.wait_group 1;" ::: "memory")
#define CP_WAIT0()  asm volatile("cp.async.wait_group 0;" ::: "memory")
#define LDSM4(r0, r1, r2, r3, addr) \
    asm volatile("ldmatrix.sync.aligned.m8n8.x4.shared.b16 {%0,%1,%2,%3}, [%4];" \
        : "=r"(r0), "=r"(r1), "=r"(r2), "=r"(r3) : "r"(addr))

__device__ __forceinline__ void mma16816(float* c, const uint32_t* a, const uint32_t* b) {
    asm volatile(
        "mma.sync.aligned.m16n8k16.row.col.f32.bf16.bf16.f32 "
        "{%0,%1,%2,%3},{%4,%5,%6,%7},{%8,%9},{%0,%1,%2,%3};"
        : "+f"(c[0]), "+f"(c[1]), "+f"(c[2]), "+f"(c[3])
        : "r"(a[0]), "r"(a[1]), "r"(a[2]), "r"(a[3]), "r"(b[0]), "r"(b[1]));
}

// ---------------- scratch (device globals; no allocation) ----------------
__device__ __align__(16) float g_x[BB*HH];
__device__ __align__(16) float g_gates[BB*H4];
__device__ __align__(16) float g_h0[BB*HH];
__device__ __align__(16) float g_c0[BB*HH];
__device__ __align__(16) float g_h1[BB*HH];
__device__ __align__(16) float g_c1[BB*HH];
__device__ __align__(16) float g_g[BB*HH];
__device__ int g_tok[BB];
// triplet-expanded bf16 operands (A: [hi,lo,hi], B: [hi,hi,lo])
__device__ __align__(16) __nv_bfloat16 g_A1[(size_t)MM*KP1];   // 50 MB
__device__ __align__(16) __nv_bfloat16 g_B1[(size_t)HH*KP1];   // 2 MB
__device__ __align__(16) __nv_bfloat16 g_A2[(size_t)MM*KP2];   // 63 MB
__device__ __align__(16) __nv_bfloat16 g_B2[(size_t)VV*KP2];   // 15.7 MB

// ---------------- token sniff ----------------
__global__ void k_tok(const int* __restrict__ t)
{
    if (threadIdx.x == 0) {
        bool is64 = true;
        #pragma unroll
        for (int i = 1; i < 32; i += 2)
            if (t[i] != 0) { is64 = false; break; }
        for (int b = 0; b < BB; b++) {
            int tok = is64 ? t[2*b] : t[b];
            if (tok < 0) tok = 0;
            if (tok >= VV) tok = VV - 1;
            g_tok[b] = tok;
        }
    }
}
__global__ void k_embed(const float* __restrict__ embed)
{
    int i = blockIdx.x*blockDim.x + threadIdx.x;
    if (i >= BB*HH) return;
    int b = i / HH, k = i % HH;
    g_x[i] = embed[(size_t)g_tok[b]*HH + k];
}

// ---------------- small GEMM (decoder path) ----------------
__global__ __launch_bounds__(256) void k_small(
    const float* __restrict__ A,  const float* __restrict__ A2,
    const float* __restrict__ W,  const float* __restrict__ W2,
    const float* __restrict__ b1, const float* __restrict__ b2,
    float* __restrict__ C, int N, int K)
{
    __shared__ float As [32][33];
    __shared__ float A2s[32][33];
    __shared__ float Ws [32][33];
    __shared__ float W2s[32][33];
    int tid = threadIdx.x;
    int n0  = blockIdx.x * 32;
    int m   = tid & 31;
    int nid = tid >> 5;
    int lrow = tid >> 3;
    int lcol = (tid & 7) * 4;
    bool dual = (A2 != nullptr);
    float acc[4] = {0.f, 0.f, 0.f, 0.f};
    for (int k0 = 0; k0 < K; k0 += 32) {
        float4 v = *(const float4*)(A + (size_t)lrow*K + k0 + lcol);
        As[lrow][lcol+0]=v.x; As[lrow][lcol+1]=v.y; As[lrow][lcol+2]=v.z; As[lrow][lcol+3]=v.w;
        float4 w = *(const float4*)(W + (size_t)(n0+lrow)*K + k0 + lcol);
        Ws[lrow][lcol+0]=w.x; Ws[lrow][lcol+1]=w.y; Ws[lrow][lcol+2]=w.z; Ws[lrow][lcol+3]=w.w;
        if (dual) {
            float4 v2 = *(const float4*)(A2 + (size_t)lrow*K + k0 + lcol);
            A2s[lrow][lcol+0]=v2.x; A2s[lrow][lcol+1]=v2.y; A2s[lrow][lcol+2]=v2.z; A2s[lrow][lcol+3]=v2.w;
            float4 w2 = *(const float4*)(W2 + (size_t)(n0+lrow)*K + k0 + lcol);
            W2s[lrow][lcol+0]=w2.x; W2s[lrow][lcol+1]=w2.y; W2s[lrow][lcol+2]=w2.z; W2s[lrow][lcol+3]=w2.w;
        }
        __syncthreads();
        if (dual) {
            #pragma unroll 8
            for (int kk = 0; kk < 32; kk++) {
                float av = As[m][kk], a2v = A2s[m][kk];
                #pragma unroll
                for (int j = 0; j < 4; j++) {
                    int nl = nid + 8*j;
                    acc[j] += av * Ws[nl][kk] + a2v * W2s[nl][kk];
                }
            }
        } else {
            #pragma unroll 8
            for (int kk = 0; kk < 32; kk++) {
                float av = As[m][kk];
                #pragma unroll
                for (int j = 0; j < 4; j++)
                    acc[j] += av * Ws[nid + 8*j][kk];
            }
        }
        __syncthreads();
    }
    #pragma unroll
    for (int j = 0; j < 4; j++) {
        int n = n0 + nid + 8*j;
        float bias = b1[n] + (b2 ? b2[n] : 0.f);
        C[(size_t)m*N + n] = acc[j] + bias;
    }
}

__device__ __forceinline__ float sigmf(float x) { return 1.f / (1.f + expf(-x)); }
__global__ void k_lstm_act(const float* __restrict__ gates,
                           const float* __restrict__ cin,
                           float* __restrict__ h, float* __restrict__ c)
{
    int i = blockIdx.x*blockDim.x + threadIdx.x;
    if (i >= BB*HH) return;
    int m = i / HH, j = i % HH;
    const float* gr = gates + (size_t)m*H4;
    float ig = sigmf(gr[j]);
    float fg = sigmf(gr[HH + j]);
    float gg = tanhf(gr[2*HH + j]);
    float og = sigmf(gr[3*HH + j]);
    float cn = fg * cin[i] + ig * gg;
    c[i] = cn;
    h[i] = og * tanhf(cn);
}

// ---------------- fp32 -> bf16 hi/lo ----------------
__device__ __forceinline__ void split_bf16(float v, unsigned short& hi, unsigned short& lo) {
    __nv_bfloat16 h = __float2bfloat16_rn(v);
    __nv_bfloat16 l = __float2bfloat16_rn(v - __bfloat162float(h));
    hi = __bfloat16_as_ushort(h);
    lo = __bfloat16_as_ushort(l);
}

// weights -> B-side triplet [hi, hi, lo]
__global__ void k_wtrip(const float* __restrict__ in,
                        __nv_bfloat16* __restrict__ outp, int N, int K)
{
    int i = blockIdx.x*blockDim.x + threadIdx.x;
    if (i >= N*K) return;
    int n = i / K, k = i % K;
    unsigned short h, l;
    split_bf16(in[i], h, l);
    char* p = (char*)outp + ((size_t)n*3*K + 3*k)*2;
    *(unsigned short*)(p + 0) = h;
    *(unsigned short*)(p + 2) = h;
    *(unsigned short*)(p + 4) = l;
}

// enc [B][D][T] fp32 -> A-side triplet [B*T][3D] = [hi, lo, hi]
__global__ void k_encT(const float* __restrict__ enc)
{
    __shared__ float tile[32][33];
    int b  = blockIdx.z;
    int d0 = blockIdx.y * 32;
    int t0 = blockIdx.x * 32;
    int tx = threadIdx.x, ty = threadIdx.y;   // (32, 8)
    const float* src = enc + ((size_t)b*DENC + d0)*TT + t0;
    #pragma unroll
    for (int j = 0; j < 4; j++)
        tile[ty + 8*j][tx] = src[(size_t)(ty + 8*j)*TT + tx];
    __syncthreads();
    #pragma unroll
    for (int j = 0; j < 4; j++) {
        int tl = ty + 8*j;
        size_t m = (size_t)b*TT + t0 + tl;
        unsigned short h, l;
        split_bf16(tile[tx][tl], h, l);
        char* p = (char*)g_A1 + (m*KP1 + 3*(size_t)(d0 + tx))*2;
        *(unsigned short*)(p + 0) = h;
        *(unsigned short*)(p + 2) = l;
        *(unsigned short*)(p + 4) = h;
    }
}

// ---------------- HMMA GEMM: 128x128 tile, 256 thr, mma.sync bf16 ----------------
// MODE 0: C = A1 @ B1^T ; epilogue relu(acc + bias + gvec[b]) -> g_A2 triplets
// MODE 1: C = A2 @ B2^T ; epilogue acc + bias -> outf fp32
#define ROWB   80        // padded smem row stride (64B data + 16B pad)
#define TILEB  (128*ROWB) // 10240 per operand
#define STAGEB (2*TILEB)  // 20480 per stage

template<int KP, int MODE>
__global__ __launch_bounds__(256, 2) void k_hmma(
    const __nv_bfloat16* __restrict__ A, const __nv_bfloat16* __restrict__ B,
    const float* __restrict__ bias, const float* __restrict__ gvec,
    float* __restrict__ outf)
{
    __shared__ __align__(16) char sb[2][STAGEB];
    const uint32_t sbase = smem_u32(sb);

    const int tid = threadIdx.x;
    const int wid = tid >> 5;
    const int lid = tid & 31;
    const int n0 = blockIdx.x * 128;
    const int m0 = blockIdx.y * 128;
    const int wm = (wid & 3) * 32;   // warp m offset (4 warp-rows)
    const int wn = (wid >> 2) * 64;  // warp n offset (2 warp-cols)

    // per-lane ldmatrix address offsets (within a stage)
    const int q   = lid >> 3;        // 0..3 submatrix
    const int lr8 = lid & 7;
    uint32_t offA[2], offB[4];
    #pragma unroll
    for (int mi = 0; mi < 2; mi++)
        offA[mi] = (uint32_t)((wm + mi*16 + (q&1)*8 + lr8)*ROWB + (q>>1)*16);
    #pragma unroll
    for (int n2 = 0; n2 < 4; n2++)
        offB[n2] = (uint32_t)(TILEB + (wn + n2*16 + (q>>1)*8 + lr8)*ROWB + (q&1)*16);

    float acc[2][8][4];
    #pragma unroll
    for (int mi = 0; mi < 2; mi++)
        #pragma unroll
        for (int ni = 0; ni < 8; ni++)
            #pragma unroll
            for (int v = 0; v < 4; v++) acc[mi][ni][v] = 0.f;

    const int r_ld = tid >> 2;        // 0..63 base row for cp.async
    const int c_ld = tid & 3;         // 16B segment
    const int nch = KP / 32;

    // prologue: chunk 0 -> stage 0
    {
        const __nv_bfloat16* ga = A + (size_t)(m0 + r_ld)*KP + c_ld*8;
        const __nv_bfloat16* gb = B + (size_t)(n0 + r_ld)*KP + c_ld*8;
        uint32_t sa = sbase + r_ld*ROWB + c_ld*16;
        CP_ASYNC16(sa, ga);
        CP_ASYNC16(sa + TILEB, gb);
        CP_ASYNC16(sa + 64*ROWB, ga + (size_t)64*KP);
        CP_ASYNC16(sa + TILEB + 64*ROWB, gb + (size_t)64*KP);
        CP_COMMIT();
    }

    for (int ch = 0; ch < nch; ch++) {
        const int st = ch & 1;
        if (ch + 1 < nch) {
            const int k0 = (ch + 1) * 32;
            const int st2 = (ch + 1) & 1;
            const __nv_bfloat16* ga = A + (size_t)(m0 + r_ld)*KP + k0 + c_ld*8;
            const __nv_bfloat16* gb = B + (size_t)(n0 + r_ld)*KP + k0 + c_ld*8;
            uint32_t sa = sbase + st2*STAGEB + r_ld*ROWB + c_ld*16;
            CP_ASYNC16(sa, ga);
            CP_ASYNC16(sa + TILEB, gb);
            CP_ASYNC16(sa + 64*ROWB, ga + (size_t)64*KP);
            CP_ASYNC16(sa + TILEB + 64*ROWB, gb + (size_t)64*KP);
            CP_COMMIT();
            CP_WAIT1();
        } else {
            CP_WAIT0();
        }
        __syncthreads();

        const uint32_t stb = sbase + st*STAGEB;
        #pragma unroll
        for (int ks = 0; ks < 2; ks++) {
            const uint32_t kb = ks * 32;
            uint32_t af[2][4];
            #pragma unroll
            for (int mi = 0; mi < 2; mi++)
                LDSM4(af[mi][0], af[mi][1], af[mi][2], af[mi][3], stb + offA[mi] + kb);
            uint32_t bf[8][2];
            #pragma unroll
            for (int n2 = 0; n2 < 4; n2++)
                LDSM4(bf[2*n2][0], bf[2*n2][1], bf[2*n2+1][0], bf[2*n2+1][1],
                      stb + offB[n2] + kb);
            #pragma unroll
            for (int mi = 0; mi < 2; mi++)
                #pragma unroll
                for (int ni = 0; ni < 8; ni++)
                    mma16816(acc[mi][ni], af[mi], bf[ni]);
        }
        __syncthreads();
    }

    // ---------------- epilogue ----------------
    const int lrow  = lid >> 2;
    const int lcol2 = (lid & 3) * 2;
    if (MODE == 1) {
        #pragma unroll
        for (int mi = 0; mi < 2; mi++) {
            const int gr = m0 + wm + mi*16 + lrow;
            #pragma unroll
            for (int ni = 0; ni < 8; ni++) {
                const int gc = n0 + wn + ni*8 + lcol2;
                const float b0 = bias[gc], b1 = bias[gc+1];
                float2 v0 = {acc[mi][ni][0] + b0, acc[mi][ni][1] + b1};
                float2 v1 = {acc[mi][ni][2] + b0, acc[mi][ni][3] + b1};
                *(float2*)&outf[(size_t)gr*VV + gc]     = v0;
                *(float2*)&outf[(size_t)(gr+8)*VV + gc] = v1;
            }
        }
    } else {
        const int b = m0 >> 9;
        const float* gv = gvec + b*HH;
        #pragma unroll
        for (int mi = 0; mi < 2; mi++) {
            const int gr = m0 + wm + mi*16 + lrow;
            #pragma unroll
            for (int ni = 0; ni < 8; ni++) {
                const int gc = n0 + wn + ni*8 + lcol2;   // always even
                const float add0 = bias[gc]   + gv[gc];
                const float add1 = bias[gc+1] + gv[gc+1];
                #pragma unroll
                for (int half = 0; half < 2; half++) {
                    const int r = gr + half*8;
                    float v0 = fmaxf(acc[mi][ni][2*half+0] + add0, 0.f);
                    float v1 = fmaxf(acc[mi][ni][2*half+1] + add1, 0.f);
                    unsigned short h0, l0, h1, l1;
                    split_bf16(v0, h0, l0);
                    split_bf16(v1, h1, l1);
                    char* p = (char*)g_A2 + ((size_t)r*KP2 + 3*(size_t)gc)*2;
                    *(uint32_t*)(p + 0) = (uint32_t)h0 | ((uint32_t)l0 << 16); // hi0, lo0
                    *(unsigned short*)(p + 4) = h0;                            // hi0
                    *(unsigned short*)(p + 6) = h1;                            // hi1
                    *(uint32_t*)(p + 8) = (uint32_t)l1 | ((uint32_t)h1 << 16); // lo1, hi1
                }
            }
        }
    }
}

// ---------------- tail ----------------
__global__ void k_tail(const int* __restrict__ tlen, float* __restrict__ out,
                       size_t out_cap)
{
    size_t i = blockIdx.x*blockDim.x + threadIdx.x;
    size_t idx = OUT0 + i;
    if (idx >= out_cap) return;
    if (i < 32) { out[idx] = (float)tlen[i]; return; }
    size_t j = i - 32;
    const size_t S = BB*HH;
    if (j < S)            out[idx] = g_h0[j];
    else if (j < 2*S)     out[idx] = g_h1[j - S];
    else if (j < 3*S)     out[idx] = g_c0[j - 2*S];
    else if (j < 4*S)     out[idx] = g_c1[j - 3*S];
}

// ---------------- launch ----------------
extern "C" void kernel_launch(void* const* d_in, const int* in_sizes, int n_in,
                              void* d_out, int out_size)
{
    const float*      enc    = (const float*)d_in[0];
    const int*        tgt32  = (const int*)d_in[1];
    const int*        tlen   = (const int*)d_in[2];
    const float*      is1    = (const float*)d_in[3];
    const float*      is2    = (const float*)d_in[4];
    const float*      wih0   = (const float*)d_in[5];
    const float*      whh0   = (const float*)d_in[6];
    const float*      bih0   = (const float*)d_in[7];
    const float*      bhh0   = (const float*)d_in[8];
    const float*      wih1   = (const float*)d_in[9];
    const float*      whh1   = (const float*)d_in[10];
    const float*      bih1   = (const float*)d_in[11];
    const float*      bhh1   = (const float*)d_in[12];
    const float*      embed  = (const float*)d_in[13];
    const float*      wenc   = (const float*)d_in[14];
    const float*      benc   = (const float*)d_in[15];
    const float*      wpred  = (const float*)d_in[16];
    const float*      bpred  = (const float*)d_in[17];
    const float*      wout   = (const float*)d_in[18];
    const float*      bout   = (const float*)d_in[19];
    float*            out    = (float*)d_out;

    float *x, *gates, *h0, *c0, *h1, *c1, *gj;
    cudaGetSymbolAddress((void**)&x,     g_x);
    cudaGetSymbolAddress((void**)&gates, g_gates);
    cudaGetSymbolAddress((void**)&h0,    g_h0);
    cudaGetSymbolAddress((void**)&c0,    g_c0);
    cudaGetSymbolAddress((void**)&h1,    g_h1);
    cudaGetSymbolAddress((void**)&c1,    g_c1);
    cudaGetSymbolAddress((void**)&gj,    g_g);

    __nv_bfloat16 *a1, *b1, *a2, *b2;
    cudaGetSymbolAddress((void**)&a1, g_A1);
    cudaGetSymbolAddress((void**)&b1, g_B1);
    cudaGetSymbolAddress((void**)&a2, g_A2);
    cudaGetSymbolAddress((void**)&b2, g_B2);

    // ---- decoder path ----
    k_tok<<<1, 32>>>(tgt32);
    k_embed<<<(BB*HH + 255)/256, 256>>>(embed);
    k_small<<<H4/32, 256>>>(x,  is1,           wih0, whh0, bih0, bhh0, gates, H4, HH);
    k_lstm_act<<<(BB*HH + 255)/256, 256>>>(gates, is2,           h0, c0);
    k_small<<<H4/32, 256>>>(h0, is1 + BB*HH,   wih1, whh1, bih1, bhh1, gates, H4, HH);
    k_lstm_act<<<(BB*HH + 255)/256, 256>>>(gates, is2 + BB*HH,   h1, c1);
    k_small<<<HH/32, 256>>>(h1, nullptr, wpred, nullptr, bpred, nullptr, gj, HH, HH);

    // ---- operand staging (triplet expansion) ----
    k_encT<<<dim3(TT/32, DENC/32, BB), dim3(32, 8)>>>(enc);
    k_wtrip<<<(HH*DENC + 255)/256, 256>>>(wenc, b1, HH, DENC);
    k_wtrip<<<(VV*HH + 255)/256, 256>>>(wout, b2, VV, HH);

    // ---- joint network on tensor cores (mma.sync bf16, K-expanded split) ----
    k_hmma<KP1, 0><<<dim3(HH/128, MM/128), 256>>>(a1, b1, benc, gj, nullptr);
    k_hmma<KP2, 1><<<dim3(VV/128, MM/128), 256>>>(a2, b2, bout, nullptr, out);

    // ---- extra tuple outputs ----
    size_t cap = (size_t)out_size;
    if (cap > OUT0) {
        size_t tail_n = cap - OUT0;
        k_tail<<<(int)((tail_n + 255)/256), 256>>>(tlen, out, cap);
    }
}

// round 9
// speedup vs baseline: 2.2209x; 1.1161x over previous
#include <cuda_runtime.h>
#include <cuda_bf16.h>
#include <math.h>
#include <stdint.h>

// ---------------- problem constants ----------------
#define BB   32
#define TT   512
#define DENC 512
#define HH   640
#define VV   4096
#define MM   (BB*TT)        // 16384
#define H4   (4*HH)         // 2560
#define OUT0 ((size_t)MM*VV) // 67108864
#define K1   DENC           // 512
#define K2   HH             // 640

// ---------------- PTX helpers ----------------
__device__ __forceinline__ uint32_t smem_u32(const void* p) {
    uint32_t a;
    asm("{ .reg .u64 t; cvta.to.shared.u64 t, %1; cvt.u32.u64 %0, t; }" : "=r"(a) : "l"(p));
    return a;
}
#define CP_ASYNC16(sa, ga) \
    asm volatile("cp.async.cg.shared.global [%0], [%1], 16;" :: "r"(sa), "l"(ga))
#define CP_COMMIT() asm volatile("cp.async.commit_group;")
#define CP_WAIT1()  asm volatile("cp.async.wait_group 1;" ::: "memory")
#define CP_WAIT0()  asm volatile("cp.async.wait_group 0;" ::: "memory")
#define LDSM4(r0, r1, r2, r3, addr) \
    asm volatile("ldmatrix.sync.aligned.m8n8.x4.shared.b16 {%0,%1,%2,%3}, [%4];" \
        : "=r"(r0), "=r"(r1), "=r"(r2), "=r"(r3) : "r"(addr))

__device__ __forceinline__ void mma16816(float* c, const uint32_t* a, const uint32_t* b) {
    asm volatile(
        "mma.sync.aligned.m16n8k16.row.col.f32.bf16.bf16.f32 "
        "{%0,%1,%2,%3},{%4,%5,%6,%7},{%8,%9},{%0,%1,%2,%3};"
        : "+f"(c[0]), "+f"(c[1]), "+f"(c[2]), "+f"(c[3])
        : "r"(a[0]), "r"(a[1]), "r"(a[2]), "r"(a[3]), "r"(b[0]), "r"(b[1]));
}

// ---------------- scratch (device globals; no allocation) ----------------
__device__ __align__(16) float g_x[BB*HH];
__device__ __align__(16) float g_gates[BB*H4];
__device__ __align__(16) float g_h0[BB*HH];
__device__ __align__(16) float g_c0[BB*HH];
__device__ __align__(16) float g_h1[BB*HH];
__device__ __align__(16) float g_c1[BB*HH];
__device__ __align__(16) float g_g[BB*HH];
__device__ int g_tok[BB];
// hi/lo plane-split bf16 operands
__device__ __align__(16) __nv_bfloat16 g_A1h[(size_t)MM*K1];  // 16.8 MB
__device__ __align__(16) __nv_bfloat16 g_A1l[(size_t)MM*K1];
__device__ __align__(16) __nv_bfloat16 g_B1h[(size_t)HH*K1];
__device__ __align__(16) __nv_bfloat16 g_B1l[(size_t)HH*K1];
__device__ __align__(16) __nv_bfloat16 g_A2h[(size_t)MM*K2];  // 21 MB
__device__ __align__(16) __nv_bfloat16 g_A2l[(size_t)MM*K2];
__device__ __align__(16) __nv_bfloat16 g_B2h[(size_t)VV*K2];  // 5.2 MB
__device__ __align__(16) __nv_bfloat16 g_B2l[(size_t)VV*K2];

// ---------------- token sniff ----------------
__global__ void k_tok(const int* __restrict__ t)
{
    if (threadIdx.x == 0) {
        bool is64 = true;
        #pragma unroll
        for (int i = 1; i < 32; i += 2)
            if (t[i] != 0) { is64 = false; break; }
        for (int b = 0; b < BB; b++) {
            int tok = is64 ? t[2*b] : t[b];
            if (tok < 0) tok = 0;
            if (tok >= VV) tok = VV - 1;
            g_tok[b] = tok;
        }
    }
}
__global__ void k_embed(const float* __restrict__ embed)
{
    int i = blockIdx.x*blockDim.x + threadIdx.x;
    if (i >= BB*HH) return;
    int b = i / HH, k = i % HH;
    g_x[i] = embed[(size_t)g_tok[b]*HH + k];
}

// ---------------- small GEMM (decoder path) ----------------
__global__ __launch_bounds__(256) void k_small(
    const float* __restrict__ A,  const float* __restrict__ A2,
    const float* __restrict__ W,  const float* __restrict__ W2,
    const float* __restrict__ b1, const float* __restrict__ b2,
    float* __restrict__ C, int N, int K)
{
    __shared__ float As [32][33];
    __shared__ float A2s[32][33];
    __shared__ float Ws [32][33];
    __shared__ float W2s[32][33];
    int tid = threadIdx.x;
    int n0  = blockIdx.x * 32;
    int m   = tid & 31;
    int nid = tid >> 5;
    int lrow = tid >> 3;
    int lcol = (tid & 7) * 4;
    bool dual = (A2 != nullptr);
    float acc[4] = {0.f, 0.f, 0.f, 0.f};
    for (int k0 = 0; k0 < K; k0 += 32) {
        float4 v = *(const float4*)(A + (size_t)lrow*K + k0 + lcol);
        As[lrow][lcol+0]=v.x; As[lrow][lcol+1]=v.y; As[lrow][lcol+2]=v.z; As[lrow][lcol+3]=v.w;
        float4 w = *(const float4*)(W + (size_t)(n0+lrow)*K + k0 + lcol);
        Ws[lrow][lcol+0]=w.x; Ws[lrow][lcol+1]=w.y; Ws[lrow][lcol+2]=w.z; Ws[lrow][lcol+3]=w.w;
        if (dual) {
            float4 v2 = *(const float4*)(A2 + (size_t)lrow*K + k0 + lcol);
            A2s[lrow][lcol+0]=v2.x; A2s[lrow][lcol+1]=v2.y; A2s[lrow][lcol+2]=v2.z; A2s[lrow][lcol+3]=v2.w;
            float4 w2 = *(const float4*)(W2 + (size_t)(n0+lrow)*K + k0 + lcol);
            W2s[lrow][lcol+0]=w2.x; W2s[lrow][lcol+1]=w2.y; W2s[lrow][lcol+2]=w2.z; W2s[lrow][lcol+3]=w2.w;
        }
        __syncthreads();
        if (dual) {
            #pragma unroll 8
            for (int kk = 0; kk < 32; kk++) {
                float av = As[m][kk], a2v = A2s[m][kk];
                #pragma unroll
                for (int j = 0; j < 4; j++) {
                    int nl = nid + 8*j;
                    acc[j] += av * Ws[nl][kk] + a2v * W2s[nl][kk];
                }
            }
        } else {
            #pragma unroll 8
            for (int kk = 0; kk < 32; kk++) {
                float av = As[m][kk];
                #pragma unroll
                for (int j = 0; j < 4; j++)
                    acc[j] += av * Ws[nid + 8*j][kk];
            }
        }
        __syncthreads();
    }
    #pragma unroll
    for (int j = 0; j < 4; j++) {
        int n = n0 + nid + 8*j;
        float bias = b1[n] + (b2 ? b2[n] : 0.f);
        C[(size_t)m*N + n] = acc[j] + bias;
    }
}

__device__ __forceinline__ float sigmf(float x) { return 1.f / (1.f + expf(-x)); }
__global__ void k_lstm_act(const float* __restrict__ gates,
                           const float* __restrict__ cin,
                           float* __restrict__ h, float* __restrict__ c)
{
    int i = blockIdx.x*blockDim.x + threadIdx.x;
    if (i >= BB*HH) return;
    int m = i / HH, j = i % HH;
    const float* gr = gates + (size_t)m*H4;
    float ig = sigmf(gr[j]);
    float fg = sigmf(gr[HH + j]);
    float gg = tanhf(gr[2*HH + j]);
    float og = sigmf(gr[3*HH + j]);
    float cn = fg * cin[i] + ig * gg;
    c[i] = cn;
    h[i] = og * tanhf(cn);
}

// ---------------- fp32 -> bf16 hi/lo ----------------
__device__ __forceinline__ void split_bf16(float v, unsigned short& hi, unsigned short& lo) {
    __nv_bfloat16 h = __float2bfloat16_rn(v);
    __nv_bfloat16 l = __float2bfloat16_rn(v - __bfloat162float(h));
    hi = __bfloat16_as_ushort(h);
    lo = __bfloat16_as_ushort(l);
}

// weights -> hi / lo planes (coalesced)
__global__ void k_wsplit(const float* __restrict__ in,
                         __nv_bfloat16* __restrict__ oh,
                         __nv_bfloat16* __restrict__ ol, int n)
{
    int i = blockIdx.x*blockDim.x + threadIdx.x;
    if (i >= n) return;
    unsigned short h, l;
    split_bf16(in[i], h, l);
    ((unsigned short*)oh)[i] = h;
    ((unsigned short*)ol)[i] = l;
}

// enc [B][D][T] fp32 -> [B*T][D] hi / lo planes (tiled transpose)
__global__ void k_encT(const float* __restrict__ enc)
{
    __shared__ float tile[32][33];
    int b  = blockIdx.z;
    int d0 = blockIdx.y * 32;
    int t0 = blockIdx.x * 32;
    int tx = threadIdx.x, ty = threadIdx.y;   // (32, 8)
    const float* src = enc + ((size_t)b*DENC + d0)*TT + t0;
    #pragma unroll
    for (int j = 0; j < 4; j++)
        tile[ty + 8*j][tx] = src[(size_t)(ty + 8*j)*TT + tx];
    __syncthreads();
    #pragma unroll
    for (int j = 0; j < 4; j++) {
        int tl = ty + 8*j;
        size_t m = (size_t)b*TT + t0 + tl;
        unsigned short h, l;
        split_bf16(tile[tx][tl], h, l);
        ((unsigned short*)g_A1h)[m*K1 + d0 + tx] = h;
        ((unsigned short*)g_A1l)[m*K1 + d0 + tx] = l;
    }
}

// ---------------- HMMA GEMM, hi/lo plane split ----------------
// Per K=32 chunk: load Ah, Al, Bh, Bl planes; acc += Ah*Bh + Al*Bh + Ah*Bl.
// MODE 0: epilogue relu(acc + bias + gvec[b]) -> g_A2h/g_A2l planes
// MODE 1: epilogue acc + bias -> outf fp32
#define ROWB   80         // 64B data + 16B pad
#define TILEB  (128*ROWB) // 10240 per plane
#define STAGEB (4*TILEB)  // 40960 per stage (4 planes)
#define SMEM_HM (2*STAGEB) // 81920

template<int KP, int MODE>
__global__ __launch_bounds__(256, 2) void k_hmma(
    const __nv_bfloat16* __restrict__ Ah, const __nv_bfloat16* __restrict__ Al,
    const __nv_bfloat16* __restrict__ Bh, const __nv_bfloat16* __restrict__ Bl,
    const float* __restrict__ bias, const float* __restrict__ gvec,
    float* __restrict__ outf)
{
    extern __shared__ __align__(16) char sb[];
    const uint32_t sbase = smem_u32(sb);

    const int tid = threadIdx.x;
    const int wid = tid >> 5;
    const int lid = tid & 31;

    // tile-raster swizzle: 8 m-tiles per n sweep (guarded bijection)
    int m0, n0;
    if ((gridDim.y & 7) == 0) {
        int bid = blockIdx.y * gridDim.x + blockIdx.x;
        int grp = bid / (gridDim.x * 8);
        int rem = bid % (gridDim.x * 8);
        m0 = (grp*8 + (rem & 7)) * 128;
        n0 = (rem >> 3) * 128;
    } else {
        m0 = blockIdx.y * 128;
        n0 = blockIdx.x * 128;
    }

    const int wm = (wid & 3) * 32;   // warp m offset
    const int wn = (wid >> 2) * 64;  // warp n offset

    // per-lane ldmatrix offsets within a plane
    const int q   = lid >> 3;
    const int lr8 = lid & 7;
    uint32_t offA[2], offB[4];
    #pragma unroll
    for (int mi = 0; mi < 2; mi++)
        offA[mi] = (uint32_t)((wm + mi*16 + (q&1)*8 + lr8)*ROWB + (q>>1)*16);
    #pragma unroll
    for (int n2 = 0; n2 < 4; n2++)
        offB[n2] = (uint32_t)((wn + n2*16 + (q>>1)*8 + lr8)*ROWB + (q&1)*16);

    float acc[2][8][4];
    #pragma unroll
    for (int mi = 0; mi < 2; mi++)
        #pragma unroll
        for (int ni = 0; ni < 8; ni++)
            #pragma unroll
            for (int v = 0; v < 4; v++) acc[mi][ni][v] = 0.f;

    const int r_ld = tid >> 2;   // 0..63
    const int c_ld = tid & 3;    // 16B segment
    const int nch = KP / 32;

    // stage loader: plane order Ah(0) Al(1) Bh(2) Bl(3)
    auto load_stage = [&](int k0, int st) {
        uint32_t sa = sbase + st*STAGEB + r_ld*ROWB + c_ld*16;
        const __nv_bfloat16* g0 = Ah + (size_t)(m0 + r_ld)*KP + k0 + c_ld*8;
        const __nv_bfloat16* g1 = Al + (size_t)(m0 + r_ld)*KP + k0 + c_ld*8;
        const __nv_bfloat16* g2 = Bh + (size_t)(n0 + r_ld)*KP + k0 + c_ld*8;
        const __nv_bfloat16* g3 = Bl + (size_t)(n0 + r_ld)*KP + k0 + c_ld*8;
        CP_ASYNC16(sa + 0*TILEB, g0);
        CP_ASYNC16(sa + 1*TILEB, g1);
        CP_ASYNC16(sa + 2*TILEB, g2);
        CP_ASYNC16(sa + 3*TILEB, g3);
        const size_t half = (size_t)64*KP;
        CP_ASYNC16(sa + 0*TILEB + 64*ROWB, g0 + half);
        CP_ASYNC16(sa + 1*TILEB + 64*ROWB, g1 + half);
        CP_ASYNC16(sa + 2*TILEB + 64*ROWB, g2 + half);
        CP_ASYNC16(sa + 3*TILEB + 64*ROWB, g3 + half);
        CP_COMMIT();
    };

    load_stage(0, 0);

    for (int ch = 0; ch < nch; ch++) {
        const int st = ch & 1;
        if (ch + 1 < nch) {
            load_stage((ch + 1)*32, (ch + 1) & 1);
            CP_WAIT1();
        } else {
            CP_WAIT0();
        }
        __syncthreads();

        const uint32_t pAh = sbase + st*STAGEB + 0*TILEB;
        const uint32_t pAl = sbase + st*STAGEB + 1*TILEB;
        const uint32_t pBh = sbase + st*STAGEB + 2*TILEB;
        const uint32_t pBl = sbase + st*STAGEB + 3*TILEB;

        #pragma unroll
        for (int ks = 0; ks < 2; ks++) {
            const uint32_t kb = ks * 32;     // 16 cols = 32B
            uint32_t af_h[2][4], af_l[2][4], bf[8][2];
            #pragma unroll
            for (int mi = 0; mi < 2; mi++) {
                LDSM4(af_h[mi][0], af_h[mi][1], af_h[mi][2], af_h[mi][3], pAh + offA[mi] + kb);
                LDSM4(af_l[mi][0], af_l[mi][1], af_l[mi][2], af_l[mi][3], pAl + offA[mi] + kb);
            }
            #pragma unroll
            for (int n2 = 0; n2 < 4; n2++)
                LDSM4(bf[2*n2][0], bf[2*n2][1], bf[2*n2+1][0], bf[2*n2+1][1],
                      pBh + offB[n2] + kb);
            #pragma unroll
            for (int mi = 0; mi < 2; mi++)
                #pragma unroll
                for (int ni = 0; ni < 8; ni++)
                    mma16816(acc[mi][ni], af_h[mi], bf[ni]);
            #pragma unroll
            for (int mi = 0; mi < 2; mi++)
                #pragma unroll
                for (int ni = 0; ni < 8; ni++)
                    mma16816(acc[mi][ni], af_l[mi], bf[ni]);
            #pragma unroll
            for (int n2 = 0; n2 < 4; n2++)
                LDSM4(bf[2*n2][0], bf[2*n2][1], bf[2*n2+1][0], bf[2*n2+1][1],
                      pBl + offB[n2] + kb);
            #pragma unroll
            for (int mi = 0; mi < 2; mi++)
                #pragma unroll
                for (int ni = 0; ni < 8; ni++)
                    mma16816(acc[mi][ni], af_h[mi], bf[ni]);
        }
        __syncthreads();
    }

    // ---------------- epilogue ----------------
    const int lrow  = lid >> 2;
    const int lcol2 = (lid & 3) * 2;
    if (MODE == 1) {
        #pragma unroll
        for (int mi = 0; mi < 2; mi++) {
            const int gr = m0 + wm + mi*16 + lrow;
            #pragma unroll
            for (int ni = 0; ni < 8; ni++) {
                const int gc = n0 + wn + ni*8 + lcol2;
                const float b0 = bias[gc], b1 = bias[gc+1];
                float2 v0 = {acc[mi][ni][0] + b0, acc[mi][ni][1] + b1};
                float2 v1 = {acc[mi][ni][2] + b0, acc[mi][ni][3] + b1};
                *(float2*)&outf[(size_t)gr*VV + gc]     = v0;
                *(float2*)&outf[(size_t)(gr+8)*VV + gc] = v1;
            }
        }
    } else {
        const int b = m0 >> 9;
        const float* gv = gvec + b*HH;
        unsigned short* oh = (unsigned short*)g_A2h;
        unsigned short* ol = (unsigned short*)g_A2l;
        #pragma unroll
        for (int mi = 0; mi < 2; mi++) {
            const int gr = m0 + wm + mi*16 + lrow;
            #pragma unroll
            for (int ni = 0; ni < 8; ni++) {
                const int gc = n0 + wn + ni*8 + lcol2;   // even
                const float add0 = bias[gc]   + gv[gc];
                const float add1 = bias[gc+1] + gv[gc+1];
                #pragma unroll
                for (int half = 0; half < 2; half++) {
                    const int r = gr + half*8;
                    float v0 = fmaxf(acc[mi][ni][2*half+0] + add0, 0.f);
                    float v1 = fmaxf(acc[mi][ni][2*half+1] + add1, 0.f);
                    unsigned short h0, l0, h1, l1;
                    split_bf16(v0, h0, l0);
                    split_bf16(v1, h1, l1);
                    size_t idx = (size_t)r*K2 + gc;
                    *(uint32_t*)&oh[idx] = (uint32_t)h0 | ((uint32_t)h1 << 16);
                    *(uint32_t*)&ol[idx] = (uint32_t)l0 | ((uint32_t)l1 << 16);
                }
            }
        }
    }
}

// ---------------- tail ----------------
__global__ void k_tail(const int* __restrict__ tlen, float* __restrict__ out,
                       size_t out_cap)
{
    size_t i = blockIdx.x*blockDim.x + threadIdx.x;
    size_t idx = OUT0 + i;
    if (idx >= out_cap) return;
    if (i < 32) { out[idx] = (float)tlen[i]; return; }
    size_t j = i - 32;
    const size_t S = BB*HH;
    if (j < S)            out[idx] = g_h0[j];
    else if (j < 2*S)     out[idx] = g_h1[j - S];
    else if (j < 3*S)     out[idx] = g_c0[j - 2*S];
    else if (j < 4*S)     out[idx] = g_c1[j - 3*S];
}

// ---------------- launch ----------------
extern "C" void kernel_launch(void* const* d_in, const int* in_sizes, int n_in,
                              void* d_out, int out_size)
{
    const float*      enc    = (const float*)d_in[0];
    const int*        tgt32  = (const int*)d_in[1];
    const int*        tlen   = (const int*)d_in[2];
    const float*      is1    = (const float*)d_in[3];
    const float*      is2    = (const float*)d_in[4];
    const float*      wih0   = (const float*)d_in[5];
    const float*      whh0   = (const float*)d_in[6];
    const float*      bih0   = (const float*)d_in[7];
    const float*      bhh0   = (const float*)d_in[8];
    const float*      wih1   = (const float*)d_in[9];
    const float*      whh1   = (const float*)d_in[10];
    const float*      bih1   = (const float*)d_in[11];
    const float*      bhh1   = (const float*)d_in[12];
    const float*      embed  = (const float*)d_in[13];
    const float*      wenc   = (const float*)d_in[14];
    const float*      benc   = (const float*)d_in[15];
    const float*      wpred  = (const float*)d_in[16];
    const float*      bpred  = (const float*)d_in[17];
    const float*      wout   = (const float*)d_in[18];
    const float*      bout   = (const float*)d_in[19];
    float*            out    = (float*)d_out;

    float *x, *gates, *h0, *c0, *h1, *c1, *gj;
    cudaGetSymbolAddress((void**)&x,     g_x);
    cudaGetSymbolAddress((void**)&gates, g_gates);
    cudaGetSymbolAddress((void**)&h0,    g_h0);
    cudaGetSymbolAddress((void**)&c0,    g_c0);
    cudaGetSymbolAddress((void**)&h1,    g_h1);
    cudaGetSymbolAddress((void**)&c1,    g_c1);
    cudaGetSymbolAddress((void**)&gj,    g_g);

    __nv_bfloat16 *a1h, *a1l, *b1h, *b1l, *a2h, *a2l, *b2h, *b2l;
    cudaGetSymbolAddress((void**)&a1h, g_A1h);
    cudaGetSymbolAddress((void**)&a1l, g_A1l);
    cudaGetSymbolAddress((void**)&b1h, g_B1h);
    cudaGetSymbolAddress((void**)&b1l, g_B1l);
    cudaGetSymbolAddress((void**)&a2h, g_A2h);
    cudaGetSymbolAddress((void**)&a2l, g_A2l);
    cudaGetSymbolAddress((void**)&b2h, g_B2h);
    cudaGetSymbolAddress((void**)&b2l, g_B2l);

    cudaFuncSetAttribute(k_hmma<K1, 0>, cudaFuncAttributeMaxDynamicSharedMemorySize, SMEM_HM);
    cudaFuncSetAttribute(k_hmma<K2, 1>, cudaFuncAttributeMaxDynamicSharedMemorySize, SMEM_HM);

    // ---- decoder path ----
    k_tok<<<1, 32>>>(tgt32);
    k_embed<<<(BB*HH + 255)/256, 256>>>(embed);
    k_small<<<H4/32, 256>>>(x,  is1,           wih0, whh0, bih0, bhh0, gates, H4, HH);
    k_lstm_act<<<(BB*HH + 255)/256, 256>>>(gates, is2,           h0, c0);
    k_small<<<H4/32, 256>>>(h0, is1 + BB*HH,   wih1, whh1, bih1, bhh1, gates, H4, HH);
    k_lstm_act<<<(BB*HH + 255)/256, 256>>>(gates, is2 + BB*HH,   h1, c1);
    k_small<<<HH/32, 256>>>(h1, nullptr, wpred, nullptr, bpred, nullptr, gj, HH, HH);

    // ---- operand staging (hi/lo planes) ----
    k_encT<<<dim3(TT/32, DENC/32, BB), dim3(32, 8)>>>(enc);
    k_wsplit<<<(HH*DENC + 255)/256, 256>>>(wenc, b1h, b1l, HH*DENC);
    k_wsplit<<<(VV*HH + 255)/256, 256>>>(wout, b2h, b2l, VV*HH);

    // ---- joint network (mma.sync bf16, 3-term plane split) ----
    k_hmma<K1, 0><<<dim3(HH/128, MM/128), 256, SMEM_HM>>>(a1h, a1l, b1h, b1l, benc, gj, nullptr);
    k_hmma<K2, 1><<<dim3(VV/128, MM/128), 256, SMEM_HM>>>(a2h, a2l, b2h, b2l, bout, nullptr, out);

    // ---- extra tuple outputs ----
    size_t cap = (size_t)out_size;
    if (cap > OUT0) {
        size_t tail_n = cap - OUT0;
        k_tail<<<(int)((tail_n + 255)/256), 256>>>(tlen, out, cap);
    }
}

// round 10
// speedup vs baseline: 3.3324x; 1.5005x over previous
#include <cuda_runtime.h>
#include <cuda_fp16.h>
#include <math.h>
#include <stdint.h>

// ---------------- problem constants ----------------
#define BB   32
#define TT   512
#define DENC 512
#define HH   640
#define VV   4096
#define MM   (BB*TT)        // 16384
#define H4   (4*HH)         // 2560
#define OUT0 ((size_t)MM*VV) // 67108864
#define K1   DENC           // 512
#define K2   HH             // 640

// ---------------- PTX helpers ----------------
__device__ __forceinline__ uint32_t smem_u32(const void* p) {
    uint32_t a;
    asm("{ .reg .u64 t; cvta.to.shared.u64 t, %1; cvt.u32.u64 %0, t; }" : "=r"(a) : "l"(p));
    return a;
}
#define CP_ASYNC16(sa, ga) \
    asm volatile("cp.async.cg.shared.global [%0], [%1], 16;" :: "r"(sa), "l"(ga))
#define CP_COMMIT() asm volatile("cp.async.commit_group;")
#define CP_WAIT1()  asm volatile("cp.async.wait_group 1;" ::: "memory")
#define CP_WAIT0()  asm volatile("cp.async.wait_group 0;" ::: "memory")
#define LDSM4(r0, r1, r2, r3, addr) \
    asm volatile("ldmatrix.sync.aligned.m8n8.x4.shared.b16 {%0,%1,%2,%3}, [%4];" \
        : "=r"(r0), "=r"(r1), "=r"(r2), "=r"(r3) : "r"(addr))

__device__ __forceinline__ void mma16816(float* c, const uint32_t* a, const uint32_t* b) {
    asm volatile(
        "mma.sync.aligned.m16n8k16.row.col.f32.f16.f16.f32 "
        "{%0,%1,%2,%3},{%4,%5,%6,%7},{%8,%9},{%0,%1,%2,%3};"
        : "+f"(c[0]), "+f"(c[1]), "+f"(c[2]), "+f"(c[3])
        : "r"(a[0]), "r"(a[1]), "r"(a[2]), "r"(a[3]), "r"(b[0]), "r"(b[1]));
}

// ---------------- scratch (device globals; no allocation) ----------------
__device__ __align__(16) float g_x[BB*HH];
__device__ __align__(16) float g_h0[BB*HH];
__device__ __align__(16) float g_c0[BB*HH];
__device__ __align__(16) float g_h1[BB*HH];
__device__ __align__(16) float g_c1[BB*HH];
__device__ __align__(16) float g_g[BB*HH];
// fp16 single-plane operands
__device__ __align__(16) __half g_A1[(size_t)MM*K1];  // 16.8 MB
__device__ __align__(16) __half g_B1[(size_t)HH*K1];
__device__ __align__(16) __half g_A2[(size_t)MM*K2];  // 21 MB
__device__ __align__(16) __half g_B2[(size_t)VV*K2];  // 5.2 MB

// ---------------- embed (with inline int64/int32 sniff) ----------------
// targets is int64 in the reference but JAX (x64 off) may materialize int32.
// LE int64 tokens < 2^31 have all odd 32-bit words zero in the first 128 B;
// random int32 tokens in [0,4096) do not.
__global__ void k_embed(const int* __restrict__ t, const float* __restrict__ embed)
{
    int i = blockIdx.x*blockDim.x + threadIdx.x;
    if (i >= BB*HH) return;
    bool is64 = true;
    #pragma unroll
    for (int w = 1; w < 32; w += 2)
        if (t[w] != 0) { is64 = false; break; }
    int b = i / HH, k = i % HH;
    int tok = is64 ? t[2*b] : t[b];
    if (tok < 0) tok = 0;
    if (tok >= VV) tok = VV - 1;
    g_x[i] = embed[(size_t)tok*HH + k];
}

// ---------------- fused LSTM cell: gates GEMM + activation ----------------
// block = 32 H-columns (20 blocks); computes all 4 gates + pointwise update.
__global__ __launch_bounds__(256) void k_cell(
    const float* __restrict__ X,    // [32][640] layer input
    const float* __restrict__ Hp,   // [32][640] h_prev
    const float* __restrict__ Cp,   // [32][640] c_prev
    const float* __restrict__ Wih,  // [4H][640]
    const float* __restrict__ Whh,  // [4H][640]
    const float* __restrict__ bih, const float* __restrict__ bhh,
    float* __restrict__ Hn, float* __restrict__ Cn)
{
    __shared__ float xs[32][33];
    __shared__ float hs[32][33];
    __shared__ float ws[8][32][33];   // [mat*4 + gate][n][k]
    const int tid = threadIdx.x;
    const int n0  = blockIdx.x * 32;
    const int m   = tid & 31;
    const int nid = tid >> 5;          // 0..7
    const int lrow = tid >> 3;         // 0..31
    const int lcol = (tid & 7) * 4;    // 0..28

    float acc[4][4];
    #pragma unroll
    for (int gte = 0; gte < 4; gte++)
        #pragma unroll
        for (int tcol = 0; tcol < 4; tcol++) acc[gte][tcol] = 0.f;

    for (int k0 = 0; k0 < HH; k0 += 32) {
        float4 xv = *(const float4*)(X  + (size_t)lrow*HH + k0 + lcol);
        xs[lrow][lcol+0]=xv.x; xs[lrow][lcol+1]=xv.y; xs[lrow][lcol+2]=xv.z; xs[lrow][lcol+3]=xv.w;
        float4 hv = *(const float4*)(Hp + (size_t)lrow*HH + k0 + lcol);
        hs[lrow][lcol+0]=hv.x; hs[lrow][lcol+1]=hv.y; hs[lrow][lcol+2]=hv.z; hs[lrow][lcol+3]=hv.w;
        #pragma unroll
        for (int tt = 0; tt < 8; tt++) {
            const int gte = tt & 3;
            const float* W = (tt < 4) ? Wih : Whh;
            float4 wv = *(const float4*)(W + (size_t)(gte*HH + n0 + lrow)*HH + k0 + lcol);
            ws[tt][lrow][lcol+0]=wv.x; ws[tt][lrow][lcol+1]=wv.y;
            ws[tt][lrow][lcol+2]=wv.z; ws[tt][lrow][lcol+3]=wv.w;
        }
        __syncthreads();
        #pragma unroll 4
        for (int kk = 0; kk < 32; kk++) {
            float xvv = xs[m][kk], hvv = hs[m][kk];
            #pragma unroll
            for (int gte = 0; gte < 4; gte++)
                #pragma unroll
                for (int tcol = 0; tcol < 4; tcol++) {
                    int nl = nid + 8*tcol;
                    acc[gte][tcol] += xvv * ws[gte][nl][kk] + hvv * ws[4+gte][nl][kk];
                }
        }
        __syncthreads();
    }
    #pragma unroll
    for (int tcol = 0; tcol < 4; tcol++) {
        int j = n0 + nid + 8*tcol;
        float gi = acc[0][tcol] + bih[0*HH+j] + bhh[0*HH+j];
        float gf = acc[1][tcol] + bih[1*HH+j] + bhh[1*HH+j];
        float gg = acc[2][tcol] + bih[2*HH+j] + bhh[2*HH+j];
        float go = acc[3][tcol] + bih[3*HH+j] + bhh[3*HH+j];
        float i_ = 1.f / (1.f + expf(-gi));
        float f_ = 1.f / (1.f + expf(-gf));
        float g_ = tanhf(gg);
        float o_ = 1.f / (1.f + expf(-go));
        float cn = f_ * Cp[(size_t)m*HH + j] + i_ * g_;
        Cn[(size_t)m*HH + j] = cn;
        Hn[(size_t)m*HH + j] = o_ * tanhf(cn);
    }
}

// ---------------- small GEMM (pred projection only) ----------------
__global__ __launch_bounds__(256) void k_small(
    const float* __restrict__ A, const float* __restrict__ W,
    const float* __restrict__ b1, float* __restrict__ C, int N, int K)
{
    __shared__ float As[32][33];
    __shared__ float Ws[32][33];
    int tid = threadIdx.x;
    int n0  = blockIdx.x * 32;
    int m   = tid & 31;
    int nid = tid >> 5;
    int lrow = tid >> 3;
    int lcol = (tid & 7) * 4;
    float acc[4] = {0.f, 0.f, 0.f, 0.f};
    for (int k0 = 0; k0 < K; k0 += 32) {
        float4 v = *(const float4*)(A + (size_t)lrow*K + k0 + lcol);
        As[lrow][lcol+0]=v.x; As[lrow][lcol+1]=v.y; As[lrow][lcol+2]=v.z; As[lrow][lcol+3]=v.w;
        float4 w = *(const float4*)(W + (size_t)(n0+lrow)*K + k0 + lcol);
        Ws[lrow][lcol+0]=w.x; Ws[lrow][lcol+1]=w.y; Ws[lrow][lcol+2]=w.z; Ws[lrow][lcol+3]=w.w;
        __syncthreads();
        #pragma unroll 8
        for (int kk = 0; kk < 32; kk++) {
            float av = As[m][kk];
            #pragma unroll
            for (int j = 0; j < 4; j++)
                acc[j] += av * Ws[nid + 8*j][kk];
        }
        __syncthreads();
    }
    #pragma unroll
    for (int j = 0; j < 4; j++) {
        int n = n0 + nid + 8*j;
        C[(size_t)m*N + n] = acc[j] + b1[n];
    }
}

// ---------------- fused staging: encT + both weight fp16 conversions ----------------
#define NB_ENC  8192                      // (DENC/32)*(TT/32)*BB
#define NB_WENC 320                       // HH*DENC/1024
#define NB_WOUT 2560                      // VV*HH/1024
__global__ __launch_bounds__(256) void k_stage(
    const float* __restrict__ enc, const float* __restrict__ wenc,
    const float* __restrict__ wout)
{
    __shared__ float tile[32][33];
    const int b = blockIdx.x;
    const int tid = threadIdx.x;
    if (b < NB_ENC) {
        // enc [B][D][T] -> fp16 [B*T][D]
        int bb = b >> 8;
        int rb = b & 255;
        int d0 = (rb >> 4) * 32;
        int t0 = (rb & 15) * 32;
        int tx = tid & 31, ty = tid >> 5;    // (32, 8)
        const float* src = enc + ((size_t)bb*DENC + d0)*TT + t0;
        #pragma unroll
        for (int j = 0; j < 4; j++)
            tile[ty + 8*j][tx] = src[(size_t)(ty + 8*j)*TT + tx];
        __syncthreads();
        #pragma unroll
        for (int j = 0; j < 4; j++) {
            int tl = ty + 8*j;
            size_t m = (size_t)bb*TT + t0 + tl;
            g_A1[m*K1 + d0 + tx] = __float2half_rn(tile[tx][tl]);
        }
    } else if (b < NB_ENC + NB_WENC) {
        size_t i = (size_t)(b - NB_ENC)*1024 + tid*4;
        float4 v = *(const float4*)&wenc[i];
        __half2 p0 = __floats2half2_rn(v.x, v.y);
        __half2 p1 = __floats2half2_rn(v.z, v.w);
        *(uint2*)&g_B1[i] = make_uint2(*(uint32_t*)&p0, *(uint32_t*)&p1);
    } else {
        size_t i = (size_t)(b - NB_ENC - NB_WENC)*1024 + tid*4;
        float4 v = *(const float4*)&wout[i];
        __half2 p0 = __floats2half2_rn(v.x, v.y);
        __half2 p1 = __floats2half2_rn(v.z, v.w);
        *(uint2*)&g_B2[i] = make_uint2(*(uint32_t*)&p0, *(uint32_t*)&p1);
    }
}

// ---------------- HMMA GEMM, single fp16 plane ----------------
// MODE 0: epilogue relu(acc + bias + gvec[b]) -> g_A2 fp16
// MODE 1: epilogue acc + bias -> outf fp32
#define ROWB   80          // 64B data + 16B pad
#define TILEB  (128*ROWB)  // 10240 per plane
#define STAGEB (2*TILEB)   // 20480 per stage (A + B)
#define SMEM_HM (2*STAGEB) // 40960

template<int KP, int MODE>
__global__ __launch_bounds__(256, 2) void k_hmma(
    const __half* __restrict__ A, const __half* __restrict__ B,
    const float* __restrict__ bias, const float* __restrict__ gvec,
    float* __restrict__ outf)
{
    extern __shared__ __align__(16) char sb[];
    const uint32_t sbase = smem_u32(sb);

    const int tid = threadIdx.x;
    const int wid = tid >> 5;
    const int lid = tid & 31;

    // tile-raster swizzle: 8 m-tiles per n sweep (guarded bijection)
    int m0, n0;
    if ((gridDim.y & 7) == 0) {
        int bid = blockIdx.y * gridDim.x + blockIdx.x;
        int grp = bid / (gridDim.x * 8);
        int rem = bid % (gridDim.x * 8);
        m0 = (grp*8 + (rem & 7)) * 128;
        n0 = (rem >> 3) * 128;
    } else {
        m0 = blockIdx.y * 128;
        n0 = blockIdx.x * 128;
    }

    const int wm = (wid & 3) * 32;   // warp m offset
    const int wn = (wid >> 2) * 64;  // warp n offset

    const int q   = lid >> 3;
    const int lr8 = lid & 7;
    uint32_t offA[2], offB[4];
    #pragma unroll
    for (int mi = 0; mi < 2; mi++)
        offA[mi] = (uint32_t)((wm + mi*16 + (q&1)*8 + lr8)*ROWB + (q>>1)*16);
    #pragma unroll
    for (int n2 = 0; n2 < 4; n2++)
        offB[n2] = (uint32_t)(TILEB + (wn + n2*16 + (q>>1)*8 + lr8)*ROWB + (q&1)*16);

    float acc[2][8][4];
    #pragma unroll
    for (int mi = 0; mi < 2; mi++)
        #pragma unroll
        for (int ni = 0; ni < 8; ni++)
            #pragma unroll
            for (int v = 0; v < 4; v++) acc[mi][ni][v] = 0.f;

    const int r_ld = tid >> 2;
    const int c_ld = tid & 3;
    const int nch = KP / 32;

    auto load_stage = [&](int k0, int st) {
        uint32_t sa = sbase + st*STAGEB + r_ld*ROWB + c_ld*16;
        const __half* gA = A + (size_t)(m0 + r_ld)*KP + k0 + c_ld*8;
        const __half* gB = B + (size_t)(n0 + r_ld)*KP + k0 + c_ld*8;
        CP_ASYNC16(sa,          gA);
        CP_ASYNC16(sa + TILEB,  gB);
        const size_t half_off = (size_t)64*KP;
        CP_ASYNC16(sa + 64*ROWB,         gA + half_off);
        CP_ASYNC16(sa + TILEB + 64*ROWB, gB + half_off);
        CP_COMMIT();
    };

    load_stage(0, 0);

    for (int ch = 0; ch < nch; ch++) {
        const int st = ch & 1;
        if (ch + 1 < nch) {
            load_stage((ch + 1)*32, (ch + 1) & 1);
            CP_WAIT1();
        } else {
            CP_WAIT0();
        }
        __syncthreads();

        const uint32_t pS = sbase + st*STAGEB;
        #pragma unroll
        for (int ks = 0; ks < 2; ks++) {
            const uint32_t kb = ks * 32;
            uint32_t af[2][4], bf[8][2];
            #pragma unroll
            for (int mi = 0; mi < 2; mi++)
                LDSM4(af[mi][0], af[mi][1], af[mi][2], af[mi][3], pS + offA[mi] + kb);
            #pragma unroll
            for (int n2 = 0; n2 < 4; n2++)
                LDSM4(bf[2*n2][0], bf[2*n2][1], bf[2*n2+1][0], bf[2*n2+1][1],
                      pS + offB[n2] + kb);
            #pragma unroll
            for (int mi = 0; mi < 2; mi++)
                #pragma unroll
                for (int ni = 0; ni < 8; ni++)
                    mma16816(acc[mi][ni], af[mi], bf[ni]);
        }
        __syncthreads();
    }

    // ---------------- epilogue ----------------
    const int lrow  = lid >> 2;
    const int lcol2 = (lid & 3) * 2;
    if (MODE == 1) {
        #pragma unroll
        for (int mi = 0; mi < 2; mi++) {
            const int gr = m0 + wm + mi*16 + lrow;
            #pragma unroll
            for (int ni = 0; ni < 8; ni++) {
                const int gc = n0 + wn + ni*8 + lcol2;
                const float b0 = bias[gc], b1 = bias[gc+1];
                float2 v0 = {acc[mi][ni][0] + b0, acc[mi][ni][1] + b1};
                float2 v1 = {acc[mi][ni][2] + b0, acc[mi][ni][3] + b1};
                *(float2*)&outf[(size_t)gr*VV + gc]     = v0;
                *(float2*)&outf[(size_t)(gr+8)*VV + gc] = v1;
            }
        }
    } else {
        const int b = m0 >> 9;
        const float* gv = gvec + b*HH;
        unsigned short* oh = (unsigned short*)g_A2;
        #pragma unroll
        for (int mi = 0; mi < 2; mi++) {
            const int gr = m0 + wm + mi*16 + lrow;
            #pragma unroll
            for (int ni = 0; ni < 8; ni++) {
                const int gc = n0 + wn + ni*8 + lcol2;   // even
                const float add0 = bias[gc]   + gv[gc];
                const float add1 = bias[gc+1] + gv[gc+1];
                #pragma unroll
                for (int half = 0; half < 2; half++) {
                    const int r = gr + half*8;
                    float v0 = fmaxf(acc[mi][ni][2*half+0] + add0, 0.f);
                    float v1 = fmaxf(acc[mi][ni][2*half+1] + add1, 0.f);
                    __half h0 = __float2half_rn(v0);
                    __half h1 = __float2half_rn(v1);
                    uint32_t pk = (uint32_t)*(unsigned short*)&h0
                                | ((uint32_t)*(unsigned short*)&h1 << 16);
                    *(uint32_t*)&oh[(size_t)r*K2 + gc] = pk;
                }
            }
        }
    }
}

// ---------------- tail ----------------
__global__ void k_tail(const int* __restrict__ tlen, float* __restrict__ out,
                       size_t out_cap)
{
    size_t i = blockIdx.x*blockDim.x + threadIdx.x;
    size_t idx = OUT0 + i;
    if (idx >= out_cap) return;
    if (i < 32) { out[idx] = (float)tlen[i]; return; }
    size_t j = i - 32;
    const size_t S = BB*HH;
    if (j < S)            out[idx] = g_h0[j];
    else if (j < 2*S)     out[idx] = g_h1[j - S];
    else if (j < 3*S)     out[idx] = g_c0[j - 2*S];
    else if (j < 4*S)     out[idx] = g_c1[j - 3*S];
}

// ---------------- launch ----------------
extern "C" void kernel_launch(void* const* d_in, const int* in_sizes, int n_in,
                              void* d_out, int out_size)
{
    const float*      enc    = (const float*)d_in[0];
    const int*        tgt32  = (const int*)d_in[1];
    const int*        tlen   = (const int*)d_in[2];
    const float*      is1    = (const float*)d_in[3];
    const float*      is2    = (const float*)d_in[4];
    const float*      wih0   = (const float*)d_in[5];
    const float*      whh0   = (const float*)d_in[6];
    const float*      bih0   = (const float*)d_in[7];
    const float*      bhh0   = (const float*)d_in[8];
    const float*      wih1   = (const float*)d_in[9];
    const float*      whh1   = (const float*)d_in[10];
    const float*      bih1   = (const float*)d_in[11];
    const float*      bhh1   = (const float*)d_in[12];
    const float*      embed  = (const float*)d_in[13];
    const float*      wenc   = (const float*)d_in[14];
    const float*      benc   = (const float*)d_in[15];
    const float*      wpred  = (const float*)d_in[16];
    const float*      bpred  = (const float*)d_in[17];
    const float*      wout   = (const float*)d_in[18];
    const float*      bout   = (const float*)d_in[19];
    float*            out    = (float*)d_out;

    float *x, *h0, *c0, *h1, *c1, *gj;
    cudaGetSymbolAddress((void**)&x,  g_x);
    cudaGetSymbolAddress((void**)&h0, g_h0);
    cudaGetSymbolAddress((void**)&c0, g_c0);
    cudaGetSymbolAddress((void**)&h1, g_h1);
    cudaGetSymbolAddress((void**)&c1, g_c1);
    cudaGetSymbolAddress((void**)&gj, g_g);

    __half *a1, *b1, *a2, *b2;
    cudaGetSymbolAddress((void**)&a1, g_A1);
    cudaGetSymbolAddress((void**)&b1, g_B1);
    cudaGetSymbolAddress((void**)&a2, g_A2);
    cudaGetSymbolAddress((void**)&b2, g_B2);

    cudaFuncSetAttribute(k_hmma<K1, 0>, cudaFuncAttributeMaxDynamicSharedMemorySize, SMEM_HM);
    cudaFuncSetAttribute(k_hmma<K2, 1>, cudaFuncAttributeMaxDynamicSharedMemorySize, SMEM_HM);

    // #0: embed (with dtype sniff)
    k_embed<<<(BB*HH + 255)/256, 256>>>(tgt32, embed);
    // #1, #2: fused LSTM cells
    k_cell<<<HH/32, 256>>>(x,  is1,          is2,          wih0, whh0, bih0, bhh0, h0, c0);
    k_cell<<<HH/32, 256>>>(h0, is1 + BB*HH,  is2 + BB*HH,  wih1, whh1, bih1, bhh1, h1, c1);
    // #3: pred projection -> g
    k_small<<<HH/32, 256>>>(h1, wpred, bpred, gj, HH, HH);
    // #4: fused staging (encT + both weight conversions)
    k_stage<<<NB_ENC + NB_WENC + NB_WOUT, 256>>>(enc, wenc, wout);
    // #5: GEMM1 (profiled by ncu -s 5 -c 1)
    k_hmma<K1, 0><<<dim3(HH/128, MM/128), 256, SMEM_HM>>>(a1, b1, benc, gj, nullptr);
    // #6: GEMM2
    k_hmma<K2, 1><<<dim3(VV/128, MM/128), 256, SMEM_HM>>>(a2, b2, bout, nullptr, out);

    // #7: extra tuple outputs
    size_t cap = (size_t)out_size;
    if (cap > OUT0) {
        size_t tail_n = cap - OUT0;
        k_tail<<<(int)((tail_n + 255)/256), 256>>>(tlen, out, cap);
    }
}

// round 12
// speedup vs baseline: 5.6395x; 1.6923x over previous
#include <cuda_runtime.h>
#include <cuda_fp16.h>
#include <math.h>
#include <stdint.h>

// ---------------- problem constants ----------------
#define BB   32
#define TT   512
#define DENC 512
#define HH   640
#define VV   4096
#define MM   (BB*TT)        // 16384
#define H4   (4*HH)         // 2560
#define OUT0 ((size_t)MM*VV) // 67108864
#define K1   DENC           // 512
#define K2   HH             // 640
#define SPL  4              // decoder K-splits

// ---------------- PTX helpers ----------------
__device__ __forceinline__ uint32_t smem_u32(const void* p) {
    uint32_t a;
    asm("{ .reg .u64 t; cvta.to.shared.u64 t, %1; cvt.u32.u64 %0, t; }" : "=r"(a) : "l"(p));
    return a;
}
#define CP_ASYNC16(sa, ga) \
    asm volatile("cp.async.cg.shared.global [%0], [%1], 16;" :: "r"(sa), "l"(ga))
#define CP_COMMIT() asm volatile("cp.async.commit_group;")
#define CP_WAIT1()  asm volatile("cp.async.wait_group 1;" ::: "memory")
#define CP_WAIT0()  asm volatile("cp.async.wait_group 0;" ::: "memory")
#define LDSM4(r0, r1, r2, r3, addr) \
    asm volatile("ldmatrix.sync.aligned.m8n8.x4.shared.b16 {%0,%1,%2,%3}, [%4];" \
        : "=r"(r0), "=r"(r1), "=r"(r2), "=r"(r3) : "r"(addr))

__device__ __forceinline__ void mma16816(float* c, const uint32_t* a, const uint32_t* b) {
    asm volatile(
        "mma.sync.aligned.m16n8k16.row.col.f32.f16.f16.f32 "
        "{%0,%1,%2,%3},{%4,%5,%6,%7},{%8,%9},{%0,%1,%2,%3};"
        : "+f"(c[0]), "+f"(c[1]), "+f"(c[2]), "+f"(c[3])
        : "r"(a[0]), "r"(a[1]), "r"(a[2]), "r"(a[3]), "r"(b[0]), "r"(b[1]));
}

// ---------------- scratch (device globals; no allocation) ----------------
__device__ __align__(16) float g_x[BB*HH];
__device__ __align__(16) float g_h0[BB*HH];
__device__ __align__(16) float g_c0[BB*HH];
__device__ __align__(16) float g_h1[BB*HH];
__device__ __align__(16) float g_c1[BB*HH];
__device__ __align__(16) float g_g[BB*HH];
__device__ __align__(16) float g_part[SPL*BB*H4];   // 1.3 MB decoder partials
// fp16 single-plane operands
__device__ __align__(16) __half g_A1[(size_t)MM*K1];  // 16.8 MB
__device__ __align__(16) __half g_B1[(size_t)HH*K1];
__device__ __align__(16) __half g_A2[(size_t)MM*K2];  // 21 MB
__device__ __align__(16) __half g_B2[(size_t)VV*K2];  // 5.2 MB

// ---------------- embed (with inline int64/int32 sniff) ----------------
__global__ void k_embed(const int* __restrict__ t, const float* __restrict__ embed)
{
    int i = blockIdx.x*blockDim.x + threadIdx.x;
    if (i >= BB*HH) return;
    bool is64 = true;
    #pragma unroll
    for (int w = 1; w < 32; w += 2)
        if (t[w] != 0) { is64 = false; break; }
    int b = i / HH, k = i % HH;
    int tok = is64 ? t[2*b] : t[b];
    if (tok < 0) tok = 0;
    if (tok >= VV) tok = VV - 1;
    g_x[i] = embed[(size_t)tok*HH + k];
}

// ---------------- decoder partial GEMM (K-split) ----------------
// part[s][32][N] = A[:, s*KS:(s+1)*KS] @ W[:, slice]^T (+ A2 @ W2^T)
// grid (N/32, SPL), 256 threads.
__global__ __launch_bounds__(256) void k_part(
    const float* __restrict__ A,  const float* __restrict__ A2,
    const float* __restrict__ W,  const float* __restrict__ W2,
    float* __restrict__ part, int N, int K)
{
    __shared__ float As [32][33];
    __shared__ float A2s[32][33];
    __shared__ float Ws [32][33];
    __shared__ float W2s[32][33];
    const int tid = threadIdx.x;
    const int n0  = blockIdx.x * 32;
    const int s   = blockIdx.y;
    const int KS  = K / SPL;
    const int kb  = s * KS;
    const int m   = tid & 31;
    const int nid = tid >> 5;
    const int lrow = tid >> 3;
    const int lcol = (tid & 7) * 4;
    const bool dual = (A2 != nullptr);

    float acc[4] = {0.f, 0.f, 0.f, 0.f};
    for (int k0 = kb; k0 < kb + KS; k0 += 32) {
        float4 v = *(const float4*)(A + (size_t)lrow*K + k0 + lcol);
        As[lrow][lcol+0]=v.x; As[lrow][lcol+1]=v.y; As[lrow][lcol+2]=v.z; As[lrow][lcol+3]=v.w;
        float4 w = *(const float4*)(W + (size_t)(n0+lrow)*K + k0 + lcol);
        Ws[lrow][lcol+0]=w.x; Ws[lrow][lcol+1]=w.y; Ws[lrow][lcol+2]=w.z; Ws[lrow][lcol+3]=w.w;
        if (dual) {
            float4 v2 = *(const float4*)(A2 + (size_t)lrow*K + k0 + lcol);
            A2s[lrow][lcol+0]=v2.x; A2s[lrow][lcol+1]=v2.y; A2s[lrow][lcol+2]=v2.z; A2s[lrow][lcol+3]=v2.w;
            float4 w2 = *(const float4*)(W2 + (size_t)(n0+lrow)*K + k0 + lcol);
            W2s[lrow][lcol+0]=w2.x; W2s[lrow][lcol+1]=w2.y; W2s[lrow][lcol+2]=w2.z; W2s[lrow][lcol+3]=w2.w;
        }
        __syncthreads();
        if (dual) {
            #pragma unroll 8
            for (int kk = 0; kk < 32; kk++) {
                float av = As[m][kk], a2v = A2s[m][kk];
                #pragma unroll
                for (int j = 0; j < 4; j++) {
                    int nl = nid + 8*j;
                    acc[j] += av * Ws[nl][kk] + a2v * W2s[nl][kk];
                }
            }
        } else {
            #pragma unroll 8
            for (int kk = 0; kk < 32; kk++) {
                float av = As[m][kk];
                #pragma unroll
                for (int j = 0; j < 4; j++)
                    acc[j] += av * Ws[nid + 8*j][kk];
            }
        }
        __syncthreads();
    }
    #pragma unroll
    for (int j = 0; j < 4; j++)
        part[((size_t)s*32 + m)*N + n0 + nid + 8*j] = acc[j];
}

// ---------------- decoder reduce + LSTM activation ----------------
__global__ void k_redcell(const float* __restrict__ part,
                          const float* __restrict__ Cp,
                          const float* __restrict__ bih, const float* __restrict__ bhh,
                          float* __restrict__ Hn, float* __restrict__ Cn)
{
    int i = blockIdx.x*blockDim.x + threadIdx.x;
    if (i >= BB*HH) return;
    int m = i / HH, j = i % HH;
    float gi = 0.f, gf = 0.f, gg = 0.f, go = 0.f;
    #pragma unroll
    for (int s = 0; s < SPL; s++) {
        const float* p = part + ((size_t)s*32 + m)*H4;
        gi += p[j]; gf += p[HH + j]; gg += p[2*HH + j]; go += p[3*HH + j];
    }
    gi += bih[j]        + bhh[j];
    gf += bih[HH + j]   + bhh[HH + j];
    gg += bih[2*HH + j] + bhh[2*HH + j];
    go += bih[3*HH + j] + bhh[3*HH + j];
    float i_ = 1.f / (1.f + expf(-gi));
    float f_ = 1.f / (1.f + expf(-gf));
    float g_ = tanhf(gg);
    float o_ = 1.f / (1.f + expf(-go));
    float cn = f_ * Cp[i] + i_ * g_;
    Cn[i] = cn;
    Hn[i] = o_ * tanhf(cn);
}

__global__ void k_redpred(const float* __restrict__ part,
                          const float* __restrict__ bias, float* __restrict__ C)
{
    int i = blockIdx.x*blockDim.x + threadIdx.x;
    if (i >= BB*HH) return;
    int m = i / HH, n = i % HH;
    float a = 0.f;
    #pragma unroll
    for (int s = 0; s < SPL; s++)
        a += part[((size_t)s*32 + m)*HH + n];
    C[i] = a + bias[n];
}

// ---------------- fused staging: encT + both weight fp16 conversions ----------------
#define NB_ENC  8192                      // (DENC/32)*(TT/32)*BB
#define NB_WENC 320                       // HH*DENC/1024
#define NB_WOUT 2560                      // VV*HH/1024
__global__ __launch_bounds__(256) void k_stage(
    const float* __restrict__ enc, const float* __restrict__ wenc,
    const float* __restrict__ wout)
{
    __shared__ float tile[32][33];
    const int b = blockIdx.x;
    const int tid = threadIdx.x;
    if (b < NB_ENC) {
        int bb = b >> 8;
        int rb = b & 255;
        int d0 = (rb >> 4) * 32;
        int t0 = (rb & 15) * 32;
        int tx = tid & 31, ty = tid >> 5;    // (32, 8)
        const float* src = enc + ((size_t)bb*DENC + d0)*TT + t0;
        #pragma unroll
        for (int j = 0; j < 4; j++)
            tile[ty + 8*j][tx] = src[(size_t)(ty + 8*j)*TT + tx];
        __syncthreads();
        #pragma unroll
        for (int j = 0; j < 4; j++) {
            int tl = ty + 8*j;
            size_t m = (size_t)bb*TT + t0 + tl;
            g_A1[m*K1 + d0 + tx] = __float2half_rn(tile[tx][tl]);
        }
    } else if (b < NB_ENC + NB_WENC) {
        size_t i = (size_t)(b - NB_ENC)*1024 + tid*4;
        float4 v = *(const float4*)&wenc[i];
        __half2 p0 = __floats2half2_rn(v.x, v.y);
        __half2 p1 = __floats2half2_rn(v.z, v.w);
        *(uint2*)&g_B1[i] = make_uint2(*(uint32_t*)&p0, *(uint32_t*)&p1);
    } else {
        size_t i = (size_t)(b - NB_ENC - NB_WENC)*1024 + tid*4;
        float4 v = *(const float4*)&wout[i];
        __half2 p0 = __floats2half2_rn(v.x, v.y);
        __half2 p1 = __floats2half2_rn(v.z, v.w);
        *(uint2*)&g_B2[i] = make_uint2(*(uint32_t*)&p0, *(uint32_t*)&p1);
    }
}

// ---------------- HMMA GEMM, single fp16 plane, 3-stage pipeline ----------------
// MODE 0: epilogue relu(acc + bias + gvec[b]) -> g_A2 fp16
// MODE 1: epilogue acc + bias -> outf fp32
#define ROWB   80          // 64B data + 16B pad
#define TILEB  (128*ROWB)  // 10240 per plane
#define STAGEB (2*TILEB)   // 20480 per stage (A + B)
#define NSTG   3
#define SMEM_HM (NSTG*STAGEB) // 61440

template<int KP, int MODE>
__global__ __launch_bounds__(256, 2) void k_hmma(
    const __half* __restrict__ A, const __half* __restrict__ B,
    const float* __restrict__ bias, const float* __restrict__ gvec,
    float* __restrict__ outf)
{
    extern __shared__ __align__(16) char sb[];
    const uint32_t sbase = smem_u32(sb);

    const int tid = threadIdx.x;
    const int wid = tid >> 5;
    const int lid = tid & 31;

    // tile-raster swizzle: 8 m-tiles per n sweep (guarded bijection)
    int m0, n0;
    if ((gridDim.y & 7) == 0) {
        int bid = blockIdx.y * gridDim.x + blockIdx.x;
        int grp = bid / (gridDim.x * 8);
        int rem = bid % (gridDim.x * 8);
        m0 = (grp*8 + (rem & 7)) * 128;
        n0 = (rem >> 3) * 128;
    } else {
        m0 = blockIdx.y * 128;
        n0 = blockIdx.x * 128;
    }

    const int wm = (wid & 3) * 32;
    const int wn = (wid >> 2) * 64;

    const int q   = lid >> 3;
    const int lr8 = lid & 7;
    uint32_t offA[2], offB[4];
    #pragma unroll
    for (int mi = 0; mi < 2; mi++)
        offA[mi] = (uint32_t)((wm + mi*16 + (q&1)*8 + lr8)*ROWB + (q>>1)*16);
    #pragma unroll
    for (int n2 = 0; n2 < 4; n2++)
        offB[n2] = (uint32_t)(TILEB + (wn + n2*16 + (q>>1)*8 + lr8)*ROWB + (q&1)*16);

    float acc[2][8][4];
    #pragma unroll
    for (int mi = 0; mi < 2; mi++)
        #pragma unroll
        for (int ni = 0; ni < 8; ni++)
            #pragma unroll
            for (int v = 0; v < 4; v++) acc[mi][ni][v] = 0.f;

    const int r_ld = tid >> 2;
    const int c_ld = tid & 3;
    const int nch = KP / 32;

    auto load_stage = [&](int k0, int st) {
        uint32_t sa = sbase + st*STAGEB + r_ld*ROWB + c_ld*16;
        const __half* gA = A + (size_t)(m0 + r_ld)*KP + k0 + c_ld*8;
        const __half* gB = B + (size_t)(n0 + r_ld)*KP + k0 + c_ld*8;
        CP_ASYNC16(sa,          gA);
        CP_ASYNC16(sa + TILEB,  gB);
        const size_t half_off = (size_t)64*KP;
        CP_ASYNC16(sa + 64*ROWB,         gA + half_off);
        CP_ASYNC16(sa + TILEB + 64*ROWB, gB + half_off);
        CP_COMMIT();
    };

    // prologue: stages 0 and 1 in flight
    load_stage(0, 0);
    if (nch > 1) load_stage(32, 1);

    for (int ch = 0; ch < nch; ch++) {
        if (ch + 1 < nch) { CP_WAIT1(); } else { CP_WAIT0(); }
        __syncthreads();   // all warps done computing previous chunk; stage ch data visible

        if (ch + 2 < nch) load_stage((ch + 2)*32, (ch + 2) % NSTG);

        const uint32_t pS = sbase + (ch % NSTG)*STAGEB;
        #pragma unroll
        for (int ks = 0; ks < 2; ks++) {
            const uint32_t kb = ks * 32;
            uint32_t af[2][4], bf[8][2];
            #pragma unroll
            for (int mi = 0; mi < 2; mi++)
                LDSM4(af[mi][0], af[mi][1], af[mi][2], af[mi][3], pS + offA[mi] + kb);
            #pragma unroll
            for (int n2 = 0; n2 < 4; n2++)
                LDSM4(bf[2*n2][0], bf[2*n2][1], bf[2*n2+1][0], bf[2*n2+1][1],
                      pS + offB[n2] + kb);
            #pragma unroll
            for (int mi = 0; mi < 2; mi++)
                #pragma unroll
                for (int ni = 0; ni < 8; ni++)
                    mma16816(acc[mi][ni], af[mi], bf[ni]);
        }
    }
    __syncthreads();

    // ---------------- epilogue ----------------
    const int lrow  = lid >> 2;
    const int lcol2 = (lid & 3) * 2;
    if (MODE == 1) {
        #pragma unroll
        for (int mi = 0; mi < 2; mi++) {
            const int gr = m0 + wm + mi*16 + lrow;
            #pragma unroll
            for (int ni = 0; ni < 8; ni++) {
                const int gc = n0 + wn + ni*8 + lcol2;
                const float b0 = bias[gc], b1 = bias[gc+1];
                float2 v0 = {acc[mi][ni][0] + b0, acc[mi][ni][1] + b1};
                float2 v1 = {acc[mi][ni][2] + b0, acc[mi][ni][3] + b1};
                *(float2*)&outf[(size_t)gr*VV + gc]     = v0;
                *(float2*)&outf[(size_t)(gr+8)*VV + gc] = v1;
            }
        }
    } else {
        const int b = m0 >> 9;
        const float* gv = gvec + b*HH;
        unsigned short* oh = (unsigned short*)g_A2;
        #pragma unroll
        for (int mi = 0; mi < 2; mi++) {
            const int gr = m0 + wm + mi*16 + lrow;
            #pragma unroll
            for (int ni = 0; ni < 8; ni++) {
                const int gc = n0 + wn + ni*8 + lcol2;   // even
                const float add0 = bias[gc]   + gv[gc];
                const float add1 = bias[gc+1] + gv[gc+1];
                #pragma unroll
                for (int half = 0; half < 2; half++) {
                    const int r = gr + half*8;
                    float v0 = fmaxf(acc[mi][ni][2*half+0] + add0, 0.f);
                    float v1 = fmaxf(acc[mi][ni][2*half+1] + add1, 0.f);
                    __half h0 = __float2half_rn(v0);
                    __half h1 = __float2half_rn(v1);
                    uint32_t pk = (uint32_t)*(unsigned short*)&h0
                                | ((uint32_t)*(unsigned short*)&h1 << 16);
                    *(uint32_t*)&oh[(size_t)r*K2 + gc] = pk;
                }
            }
        }
    }
}

// ---------------- tail ----------------
__global__ void k_tail(const int* __restrict__ tlen, float* __restrict__ out,
                       size_t out_cap)
{
    size_t i = blockIdx.x*blockDim.x + threadIdx.x;
    size_t idx = OUT0 + i;
    if (idx >= out_cap) return;
    if (i < 32) { out[idx] = (float)tlen[i]; return; }
    size_t j = i - 32;
    const size_t S = BB*HH;
    if (j < S)            out[idx] = g_h0[j];
    else if (j < 2*S)     out[idx] = g_h1[j - S];
    else if (j < 3*S)     out[idx] = g_c0[j - 2*S];
    else if (j < 4*S)     out[idx] = g_c1[j - 3*S];
}

// ---------------- launch ----------------
extern "C" void kernel_launch(void* const* d_in, const int* in_sizes, int n_in,
                              void* d_out, int out_size)
{
    const float*      enc    = (const float*)d_in[0];
    const int*        tgt32  = (const int*)d_in[1];
    const int*        tlen   = (const int*)d_in[2];
    const float*      is1    = (const float*)d_in[3];
    const float*      is2    = (const float*)d_in[4];
    const float*      wih0   = (const float*)d_in[5];
    const float*      whh0   = (const float*)d_in[6];
    const float*      bih0   = (const float*)d_in[7];
    const float*      bhh0   = (const float*)d_in[8];
    const float*      wih1   = (const float*)d_in[9];
    const float*      whh1   = (const float*)d_in[10];
    const float*      bih1   = (const float*)d_in[11];
    const float*      bhh1   = (const float*)d_in[12];
    const float*      embed  = (const float*)d_in[13];
    const float*      wenc   = (const float*)d_in[14];
    const float*      benc   = (const float*)d_in[15];
    const float*      wpred  = (const float*)d_in[16];
    const float*      bpred  = (const float*)d_in[17];
    const float*      wout   = (const float*)d_in[18];
    const float*      bout   = (const float*)d_in[19];
    float*            out    = (float*)d_out;

    float *x, *h0, *c0, *h1, *c1, *gj, *part;
    cudaGetSymbolAddress((void**)&x,    g_x);
    cudaGetSymbolAddress((void**)&h0,   g_h0);
    cudaGetSymbolAddress((void**)&c0,   g_c0);
    cudaGetSymbolAddress((void**)&h1,   g_h1);
    cudaGetSymbolAddress((void**)&c1,   g_c1);
    cudaGetSymbolAddress((void**)&gj,   g_g);
    cudaGetSymbolAddress((void**)&part, g_part);

    __half *a1, *b1, *a2, *b2;
    cudaGetSymbolAddress((void**)&a1, g_A1);
    cudaGetSymbolAddress((void**)&b1, g_B1);
    cudaGetSymbolAddress((void**)&a2, g_A2);
    cudaGetSymbolAddress((void**)&b2, g_B2);

    cudaFuncSetAttribute(k_hmma<K1, 0>, cudaFuncAttributeMaxDynamicSharedMemorySize, SMEM_HM);
    cudaFuncSetAttribute(k_hmma<K2, 1>, cudaFuncAttributeMaxDynamicSharedMemorySize, SMEM_HM);

    // decoder (K-split parallelized)
    k_embed<<<(BB*HH + 255)/256, 256>>>(tgt32, embed);
    k_part<<<dim3(H4/32, SPL), 256>>>(x,  is1,          wih0, whh0, part, H4, HH);
    k_redcell<<<(BB*HH + 255)/256, 256>>>(part, is2,          bih0, bhh0, h0, c0);
    k_part<<<dim3(H4/32, SPL), 256>>>(h0, is1 + BB*HH,  wih1, whh1, part, H4, HH);
    k_redcell<<<(BB*HH + 255)/256, 256>>>(part, is2 + BB*HH,  bih1, bhh1, h1, c1);
    k_part<<<dim3(HH/32, SPL), 256>>>(h1, nullptr, wpred, nullptr, part, HH, HH);
    k_redpred<<<(BB*HH + 255)/256, 256>>>(part, bpred, gj);

    // staging (encT + weight conversions, one kernel)
    k_stage<<<NB_ENC + NB_WENC + NB_WOUT, 256>>>(enc, wenc, wout);

    // joint network (mma.sync fp16, 3-stage pipeline)
    k_hmma<K1, 0><<<dim3(HH/128, MM/128), 256, SMEM_HM>>>(a1, b1, benc, gj, nullptr);
    k_hmma<K2, 1><<<dim3(VV/128, MM/128), 256, SMEM_HM>>>(a2, b2, bout, nullptr, out);

    // extra tuple outputs
    size_t cap = (size_t)out_size;
    if (cap > OUT0) {
        size_t tail_n = cap - OUT0;
        k_tail<<<(int)((tail_n + 255)/256), 256>>>(tlen, out, cap);
    }
}